// round 14
// baseline (speedup 1.0000x reference)
#include <cuda_runtime.h>
#include <cuda_bf16.h>
#include <cuda_fp16.h>
#include <cstdint>

#define NN 8192
#define EE 131072
#define IS3 0.5773502691896258f

// ---------------- static scratch ----------------
__device__ float g_US[NN*128];
__device__ float g_UV[NN*384];
__device__ float g_ABCD[NN*256];          // AS|AT|BS|BT
__device__ __half g_TPWh[(size_t)EE*512]; // position-ordered, fp16
__device__ float g_ED[EE];                // position-ordered
__device__ int   g_PSND[EE];              // position-ordered sender
__device__ float4 g_PEA[EE];              // position-ordered edge_attrs
__device__ float g_MSGS[NN*256];
__device__ float g_MSGV[NN*768];
__device__ float g_MS[NN*256];
__device__ float g_MV[NN*384];
__device__ int   g_CNT[NN];
__device__ int   g_OFF[NN+1];
__device__ int   g_CUR[NN];
__device__ int   g_BKT[EE];
// packed weights
__device__ float g_Wns[128*256];
__device__ float g_Wnv[128*256];
__device__ float g_Wc[10*256];
__device__ float g_Wt8[8*128];
__device__ float g_Wms[384*256];
__device__ float g_Wmv[384*128];
__device__ uint32_t g_Wr1t[64*64];        // pre-rounded tf32 bits
__device__ uint32_t g_Wr2t[64*64];
__device__ uint32_t g_Wr3t[64*512];

#define RS128 0.08838834764831845f
#define RS10  0.31622776601683794f
#define RS64  0.125f
#define RS256 0.0625f
#define RS264 0.061545745489666336f

// ---------------- tf32 helpers ----------------
__device__ __forceinline__ uint32_t f2tf(float x) {
    uint32_t u;
    asm("cvt.rna.tf32.f32 %0, %1;" : "=r"(u) : "f"(x));
    return u;
}
__device__ __forceinline__ void mma_tf32(float* c, const uint32_t* a, uint32_t b0, uint32_t b1) {
    asm volatile(
        "mma.sync.aligned.m16n8k8.row.col.f32.tf32.tf32.f32 "
        "{%0,%1,%2,%3}, {%4,%5,%6,%7}, {%8,%9}, {%0,%1,%2,%3};"
        : "+f"(c[0]), "+f"(c[1]), "+f"(c[2]), "+f"(c[3])
        : "r"(a[0]), "r"(a[1]), "r"(a[2]), "r"(a[3]), "r"(b0), "r"(b1));
}
__device__ __forceinline__ float siluf(float x) { return x / (1.f + __expf(-x)); }
__device__ __forceinline__ float sigmf(float x) { return 1.f / (1.f + __expf(-x)); }

#define AP 68
#define BP 72
#define MMA_SMEM ((128*AP + 64*BP) * 4)
#define EDGE_SMEM (MMA_SMEM + (64 + 384 + 1024 + 1024) * 4)

__device__ __forceinline__ void tile_mma64(
    const uint32_t* __restrict__ As, const uint32_t* __restrict__ Bs,
    int wr, int wc, int g, int l, float acc[2][4][4])
{
    #pragma unroll
    for (int kt = 0; kt < 8; kt++) {
        uint32_t a[2][4];
        #pragma unroll
        for (int mt = 0; mt < 2; mt++) {
            int base = (wr * 32 + mt * 16 + g) * AP + kt * 8 + l;
            a[mt][0] = As[base];
            a[mt][1] = As[base + 8 * AP];
            a[mt][2] = As[base + 4];
            a[mt][3] = As[base + 8 * AP + 4];
        }
        #pragma unroll
        for (int nt = 0; nt < 4; nt++) {
            int bcol = wc * 32 + nt * 8 + g;
            uint32_t b0 = Bs[(kt * 8 + l) * BP + bcol];
            uint32_t b1 = Bs[(kt * 8 + l + 4) * BP + bcol];
            mma_tf32(acc[0][nt], a[0], b0, b1);
            mma_tf32(acc[1][nt], a[1], b0, b1);
        }
    }
}

// ---------------- unified strided/split GEMM ----------------
__global__ void __launch_bounds__(256) mma_gemm_kernel(
    const float* __restrict__ X1, int ldx1, int sx1, int zx1,
    const float* __restrict__ X2, int ldx2, int sx2, int zx2, int K1,
    const float* __restrict__ W, int wld,
    float* __restrict__ Y1, int ldy1, int sy1, int zy1,
    float* __restrict__ Y2, int ldy2, int sy2, int zy2, int N1,
    int K, float scale)
{
    extern __shared__ uint32_t smem[];
    uint32_t* As = smem;
    uint32_t* Bs = smem + 128 * AP;

    int t  = threadIdx.x;
    int r0 = blockIdx.y * 128;
    int c0 = blockIdx.x * 64;
    int z  = blockIdx.z;

    int warp = t >> 5, lane = t & 31;
    int wr = warp >> 1, wc = warp & 1;
    int g = lane >> 2, l = lane & 3;

    float acc[2][4][4] = {};

    for (int k0 = 0; k0 < K; k0 += 64) {
        const float* Xp; int ld, sxx, kb;
        if (k0 < K1) { Xp = X1 + (size_t)z * zx1; ld = ldx1; sxx = sx1; kb = k0; }
        else         { Xp = X2 + (size_t)z * zx2; ld = ldx2; sxx = sx2; kb = k0 - K1; }
        int rem = K - k0;

        if (sxx == 1 && rem >= 64) {
            #pragma unroll
            for (int i = 0; i < 8; i++) {
                int e = t + i * 256;
                int row = e >> 4, c4 = (e & 15) * 4;
                float4 v = *reinterpret_cast<const float4*>(
                    &Xp[(size_t)(r0 + row) * ld + kb + c4]);
                uint4 u = make_uint4(f2tf(v.x), f2tf(v.y), f2tf(v.z), f2tf(v.w));
                *reinterpret_cast<uint4*>(&As[row * AP + c4]) = u;
            }
        } else {
            #pragma unroll
            for (int i = 0; i < 32; i++) {
                int e = t + i * 256;
                int row = e >> 6, col = e & 63;
                float x = (col < rem) ? Xp[(size_t)(r0 + row) * ld + (size_t)(kb + col) * sxx] : 0.f;
                As[row * AP + col] = f2tf(x);
            }
        }
        #pragma unroll
        for (int i = 0; i < 4; i++) {
            int e = t + i * 256;
            int row = e >> 4, c4 = (e & 15) * 4;
            int kk = k0 + row;
            float4 v = make_float4(0.f, 0.f, 0.f, 0.f);
            if (kk < K)
                v = *reinterpret_cast<const float4*>(&W[(size_t)kk * wld + c0 + c4]);
            uint4 u = make_uint4(f2tf(v.x), f2tf(v.y), f2tf(v.z), f2tf(v.w));
            *reinterpret_cast<uint4*>(&Bs[row * BP + c4]) = u;
        }
        __syncthreads();
        tile_mma64(As, Bs, wr, wc, g, l, acc);
        __syncthreads();
    }

    float* Yp; int ldy, syy; int colb;
    if (Y2 != nullptr && c0 >= N1) {
        Yp = Y2 + (size_t)z * zy2; ldy = ldy2; syy = sy2; colb = c0 - N1;
    } else {
        Yp = Y1 + (size_t)z * zy1; ldy = ldy1; syy = sy1; colb = c0;
    }

    #pragma unroll
    for (int mt = 0; mt < 2; mt++)
        #pragma unroll
        for (int idx = 0; idx < 4; idx++) {
            int row = r0 + wr * 32 + mt * 16 + g + ((idx >= 2) ? 8 : 0);
            #pragma unroll
            for (int nt = 0; nt < 4; nt++) {
                int col = colb + wc * 32 + nt * 8 + 2 * l + (idx & 1);
                Yp[(size_t)row * ldy + (size_t)col * syy] = acc[mt][nt][idx] * scale;
            }
        }
}

// ---------------- output GEMMs with fused activations ----------------
// f_s = silu(MS[:, :128]) @ W2_s * RS128 -> out[:, :, 0]
__global__ void __launch_bounds__(256) outs_gemm_kernel(
    const float* __restrict__ W2_s, float* __restrict__ out)
{
    extern __shared__ uint32_t smem[];
    uint32_t* As = smem;
    uint32_t* Bs = smem + 128 * AP;

    int t  = threadIdx.x;
    int r0 = blockIdx.y * 128;
    int c0 = blockIdx.x * 64;
    int warp = t >> 5, lane = t & 31;
    int wr = warp >> 1, wc = warp & 1;
    int g = lane >> 2, l = lane & 3;

    float acc[2][4][4] = {};

    #pragma unroll
    for (int k0 = 0; k0 < 128; k0 += 64) {
        #pragma unroll
        for (int i = 0; i < 8; i++) {
            int e = t + i * 256;
            int row = e >> 4, c4 = (e & 15) * 4;
            float4 v = *reinterpret_cast<const float4*>(
                &g_MS[(size_t)(r0 + row) * 256 + k0 + c4]);
            uint4 u = make_uint4(f2tf(siluf(v.x)), f2tf(siluf(v.y)),
                                 f2tf(siluf(v.z)), f2tf(siluf(v.w)));
            *reinterpret_cast<uint4*>(&As[row * AP + c4]) = u;
        }
        #pragma unroll
        for (int i = 0; i < 4; i++) {
            int e = t + i * 256;
            int row = e >> 4, c4 = (e & 15) * 4;
            float4 v = *reinterpret_cast<const float4*>(
                &W2_s[(size_t)(k0 + row) * 128 + c0 + c4]);
            uint4 u = make_uint4(f2tf(v.x), f2tf(v.y), f2tf(v.z), f2tf(v.w));
            *reinterpret_cast<uint4*>(&Bs[row * BP + c4]) = u;
        }
        __syncthreads();
        tile_mma64(As, Bs, wr, wc, g, l, acc);
        __syncthreads();
    }

    #pragma unroll
    for (int mt = 0; mt < 2; mt++)
        #pragma unroll
        for (int idx = 0; idx < 4; idx++) {
            int row = r0 + wr * 32 + mt * 16 + g + ((idx >= 2) ? 8 : 0);
            #pragma unroll
            for (int nt = 0; nt < 4; nt++) {
                int col = c0 + wc * 32 + nt * 8 + 2 * l + (idx & 1);
                out[(size_t)row * 512 + col * 4] = acc[mt][nt][idx] * RS128;
            }
        }
}

// f_v[cc] = (MV[:, :, cc] * sigmoid(MS[:, 128:])) @ W2_v * RS128 -> out[:, :, 1+cc]
__global__ void __launch_bounds__(256) outv_gemm_kernel(
    const float* __restrict__ W2_v, float* __restrict__ out)
{
    extern __shared__ uint32_t smem[];
    uint32_t* As = smem;
    uint32_t* Bs = smem + 128 * AP;

    int t  = threadIdx.x;
    int r0 = blockIdx.y * 128;
    int c0 = blockIdx.x * 64;
    int cc = blockIdx.z;
    int warp = t >> 5, lane = t & 31;
    int wr = warp >> 1, wc = warp & 1;
    int g = lane >> 2, l = lane & 3;

    float acc[2][4][4] = {};

    #pragma unroll
    for (int k0 = 0; k0 < 128; k0 += 64) {
        #pragma unroll
        for (int i = 0; i < 32; i++) {
            int e = t + i * 256;
            int row = e >> 6, col = e & 63;
            int rr = r0 + row, k = k0 + col;
            float gate = sigmf(g_MS[(size_t)rr * 256 + 128 + k]);
            float x = g_MV[(size_t)rr * 384 + k * 3 + cc] * gate;
            As[row * AP + col] = f2tf(x);
        }
        #pragma unroll
        for (int i = 0; i < 4; i++) {
            int e = t + i * 256;
            int row = e >> 4, c4 = (e & 15) * 4;
            float4 v = *reinterpret_cast<const float4*>(
                &W2_v[(size_t)(k0 + row) * 128 + c0 + c4]);
            uint4 u = make_uint4(f2tf(v.x), f2tf(v.y), f2tf(v.z), f2tf(v.w));
            *reinterpret_cast<uint4*>(&Bs[row * BP + c4]) = u;
        }
        __syncthreads();
        tile_mma64(As, Bs, wr, wc, g, l, acc);
        __syncthreads();
    }

    #pragma unroll
    for (int mt = 0; mt < 2; mt++)
        #pragma unroll
        for (int idx = 0; idx < 4; idx++) {
            int row = r0 + wr * 32 + mt * 16 + g + ((idx >= 2) ? 8 : 0);
            #pragma unroll
            for (int nt = 0; nt < 4; nt++) {
                int col = c0 + wc * 32 + nt * 8 + 2 * l + (idx & 1);
                out[(size_t)row * 512 + col * 4 + 1 + cc] = acc[mt][nt][idx] * RS128;
            }
        }
}

// ---------------- fused edge MLP (bucket-position order) ----------------
__global__ void __launch_bounds__(256) edge_mlp_kernel(
    const int* __restrict__ ei, const float* __restrict__ edge_attrs,
    const float* __restrict__ edge_feats, const float* __restrict__ Wd1)
{
    extern __shared__ uint32_t smem[];
    uint32_t* As = smem;
    uint32_t* Bs = smem + 128 * AP;
    float* sWd1 = (float*)(Bs + 64 * BP);
    int*   sSnd = (int*)(sWd1 + 64);
    int*   sRcv = sSnd + 128;
    int*   sEd  = sRcv + 128;
    float* sEf  = (float*)(sEd + 128);       // [128][8]
    float* sW8  = sEf + 128 * 8;             // [8][128]

    int t = threadIdx.x;
    int e0 = blockIdx.x * 128;               // position base
    int warp = t >> 5, lane = t & 31;
    int wr = warp >> 1, wc = warp & 1;
    int g = lane >> 2, l = lane & 3;

    if (t < 64) sWd1[t] = Wd1[t];
    if (t < 128) {
        int ed = g_BKT[e0 + t];
        sEd[t] = ed;
        int snd = ei[ed];
        sSnd[t] = snd;
        sRcv[t] = ei[EE + ed];
        g_PSND[e0 + t] = snd;
        g_PEA[e0 + t] = reinterpret_cast<const float4*>(edge_attrs)[ed];
    }
    #pragma unroll
    for (int i = 0; i < 4; i++) sW8[t + i * 256] = g_Wt8[t + i * 256];
    __syncthreads();

    // edge_feats rows by gathered index (32B per edge, L2-resident)
    {
        float4 v = *reinterpret_cast<const float4*>(
            &edge_feats[(size_t)sEd[t >> 1] * 8 + (t & 1) * 4]);
        reinterpret_cast<float4*>(sEf)[t] = v;
    }
    __syncthreads();

    // h0 = silu((ef8@W8[:, :64] + AS[snd] + AT[rcv]) * rs264) -> As
    #pragma unroll
    for (int i = 0; i < 32; i++) {
        int e = t + i * 256;
        int row = e >> 6, c = e & 63;
        float accv = 0.f;
        #pragma unroll
        for (int k = 0; k < 8; k++)
            accv = fmaf(sEf[row * 8 + k], sW8[k * 128 + c], accv);
        float h0 = (accv
                  + g_ABCD[(size_t)sSnd[row] * 256 + c]
                  + g_ABCD[(size_t)sRcv[row] * 256 + 64 + c]) * RS264;
        As[row * AP + c] = f2tf(siluf(h0));
    }
    // density head (cols 64..127 of packed W8)
    for (int el = warp; el < 128; el += 8) {
        int snd = sSnd[el], rcv = sRcv[el];
        float sum = 0.f;
        #pragma unroll
        for (int h = 0; h < 2; h++) {
            int c = lane + h * 32;
            float accv = 0.f;
            #pragma unroll
            for (int k = 0; k < 8; k++)
                accv = fmaf(sEf[el * 8 + k], sW8[k * 128 + 64 + c], accv);
            float d0 = (accv
                      + g_ABCD[(size_t)snd * 256 + 128 + c]
                      + g_ABCD[(size_t)rcv * 256 + 192 + c]) * RS264;
            sum += siluf(d0) * sWd1[c];
        }
        #pragma unroll
        for (int o = 16; o > 0; o >>= 1)
            sum += __shfl_down_sync(0xffffffff, sum, o);
        if (lane == 0) {
            float x = sum * RS64;
            g_ED[e0 + el] = tanhf(x * x);
        }
    }
    // W_r1 (pre-rounded tf32 bits: pure 16B copies)
    #pragma unroll
    for (int i = 0; i < 4; i++) {
        int e = t + i * 256;
        int row = e >> 4, c4 = (e & 15) * 4;
        uint4 u = *reinterpret_cast<const uint4*>(&g_Wr1t[row * 64 + c4]);
        *reinterpret_cast<uint4*>(&Bs[row * BP + c4]) = u;
    }
    __syncthreads();

    float acc[2][4][4] = {};
    tile_mma64(As, Bs, wr, wc, g, l, acc);
    __syncthreads();

    #pragma unroll
    for (int mt = 0; mt < 2; mt++)
        #pragma unroll
        for (int idx = 0; idx < 4; idx++) {
            int row = wr * 32 + mt * 16 + g + ((idx >= 2) ? 8 : 0);
            #pragma unroll
            for (int nt = 0; nt < 4; nt++) {
                int col = wc * 32 + nt * 8 + 2 * l + (idx & 1);
                As[row * AP + col] = f2tf(siluf(acc[mt][nt][idx] * RS64));
            }
        }
    #pragma unroll
    for (int i = 0; i < 4; i++) {
        int e = t + i * 256;
        int row = e >> 4, c4 = (e & 15) * 4;
        uint4 u = *reinterpret_cast<const uint4*>(&g_Wr2t[row * 64 + c4]);
        *reinterpret_cast<uint4*>(&Bs[row * BP + c4]) = u;
    }
    __syncthreads();

    float acc2[2][4][4] = {};
    tile_mma64(As, Bs, wr, wc, g, l, acc2);
    __syncthreads();

    #pragma unroll
    for (int mt = 0; mt < 2; mt++)
        #pragma unroll
        for (int idx = 0; idx < 4; idx++) {
            int row = wr * 32 + mt * 16 + g + ((idx >= 2) ? 8 : 0);
            #pragma unroll
            for (int nt = 0; nt < 4; nt++) {
                int col = wc * 32 + nt * 8 + 2 * l + (idx & 1);
                As[row * AP + col] = f2tf(siluf(acc2[mt][nt][idx] * RS64));
            }
        }
    __syncthreads();

    for (int ct = 0; ct < 8; ct++) {
        #pragma unroll
        for (int i = 0; i < 4; i++) {
            int e = t + i * 256;
            int row = e >> 4, c4 = (e & 15) * 4;
            uint4 u = *reinterpret_cast<const uint4*>(&g_Wr3t[row * 512 + ct * 64 + c4]);
            *reinterpret_cast<uint4*>(&Bs[row * BP + c4]) = u;
        }
        __syncthreads();
        float acc3[2][4][4] = {};
        tile_mma64(As, Bs, wr, wc, g, l, acc3);
        #pragma unroll
        for (int mt = 0; mt < 2; mt++)
            #pragma unroll
            for (int hi = 0; hi < 2; hi++) {
                int row = e0 + wr * 32 + mt * 16 + g + (hi ? 8 : 0);
                #pragma unroll
                for (int nt = 0; nt < 4; nt++) {
                    int col = ct * 64 + wc * 32 + nt * 8 + 2 * l;
                    __half2 h = __floats2half2_rn(acc3[mt][nt][hi * 2] * RS64,
                                                  acc3[mt][nt][hi * 2 + 1] * RS64);
                    *reinterpret_cast<__half2*>(&g_TPWh[(size_t)row * 512 + col]) = h;
                }
            }
        __syncthreads();
    }
}

// ---------------- weight prep (+ CNT zeroing folded in) ----------------
__global__ void __launch_bounds__(256) prep_kernel(
    const float* __restrict__ W_skip_s, const float* __restrict__ W_skip_v,
    const float* __restrict__ W_up_s,   const float* __restrict__ W_up_v,
    const float* __restrict__ W_src,    const float* __restrict__ W_tgt,
    const float* __restrict__ W_r0,     const float* __restrict__ W_d0,
    const float* __restrict__ W_r1,     const float* __restrict__ W_r2,
    const float* __restrict__ W_r3,
    const float* __restrict__ W1_s,     const float* __restrict__ W1_v,
    const float* __restrict__ Wres_s,   const float* __restrict__ Wres_v)
{
    int id = blockIdx.x * 256 + threadIdx.x;
    if (id < NN) g_CNT[id] = 0;
    if (id < 128 * 256) {
        int m = id >> 8, j = id & 255;
        g_Wns[id] = (j < 128) ? W_skip_s[m * 128 + j] : W_up_s[m * 128 + j - 128];
        g_Wnv[id] = (j < 128) ? W_skip_v[m * 128 + j] : W_up_v[m * 128 + j - 128];
    }
    if (id < 8 * 128) {
        int m = id >> 7, j = id & 127;
        g_Wt8[id] = (j < 64) ? W_r0[m * 64 + j] : W_d0[m * 64 + j - 64];
    }
    if (id < 384 * 256) {
        int k = id >> 8, j = id & 255;
        g_Wms[id] = (k < 256) ? W1_s[k * 256 + j] * RS256
                              : Wres_s[(k - 256) * 256 + j] * RS128;
    }
    if (id < 384 * 128) {
        int k = id / 128, j = id % 128;
        g_Wmv[id] = (k < 256) ? W1_v[k * 128 + j] * RS256
                              : Wres_v[(k - 256) * 128 + j] * RS128;
    }
    if (id < 64 * 64) {
        g_Wr1t[id] = f2tf(W_r1[id]);
        g_Wr2t[id] = f2tf(W_r2[id]);
    }
    if (id < 64 * 512) {
        g_Wr3t[id] = f2tf(W_r3[id]);
    }
    if (id < 10 * 256) {
        int a = id >> 8, j = id & 255;
        int q = j >> 6, jj = j & 63;
        const float* S = (q == 0 || q == 2) ? W_src : W_tgt;
        const float* M = (q < 2) ? W_r0 : W_d0;
        int off = (q == 0 || q == 2) ? 8 : 136;
        float s = 0.f;
        for (int m = 0; m < 128; m++)
            s += S[a * 128 + m] * M[(off + m) * 64 + jj];
        g_Wc[a * 256 + j] = s * RS10;
    }
}

// ---------------- bucketing ----------------
__global__ void count_kernel(const int* __restrict__ ei) {
    int e = blockIdx.x * blockDim.x + threadIdx.x;
    if (e < EE) atomicAdd(&g_CNT[ei[EE + e]], 1);
}
__global__ void __launch_bounds__(1024) scan_kernel() {
    __shared__ int wt[32];
    int t = threadIdx.x, lane = t & 31, w = t >> 5;
    int base = t * 8;
    int4 lo = reinterpret_cast<const int4*>(g_CNT)[t * 2];
    int4 hi = reinterpret_cast<const int4*>(g_CNT)[t * 2 + 1];
    int local[8] = {lo.x, lo.y, lo.z, lo.w, hi.x, hi.y, hi.z, hi.w};
    int s = 0;
    #pragma unroll
    for (int i = 0; i < 8; i++) s += local[i];
    int v = s;
    #pragma unroll
    for (int o = 1; o < 32; o <<= 1) {
        int u = __shfl_up_sync(0xffffffff, v, o);
        if (lane >= o) v += u;
    }
    if (lane == 31) wt[w] = v;
    __syncthreads();
    if (w == 0) {
        int x = wt[lane];
        #pragma unroll
        for (int o = 1; o < 32; o <<= 1) {
            int u = __shfl_up_sync(0xffffffff, x, o);
            if (lane >= o) x += u;
        }
        wt[lane] = x;
    }
    __syncthreads();
    int run = v - s + (w > 0 ? wt[w - 1] : 0);
    #pragma unroll
    for (int i = 0; i < 8; i++) { g_OFF[base + i] = run; g_CUR[base + i] = run; run += local[i]; }
    if (t == 1023) g_OFF[NN] = run;
}
__global__ void fill_kernel(const int* __restrict__ ei) {
    int e = blockIdx.x * blockDim.x + threadIdx.x;
    if (e < EE) {
        int pos = atomicAdd(&g_CUR[ei[EE + e]], 1);
        g_BKT[pos] = e;
    }
}
__global__ void sort_kernel() {
    int n = blockIdx.x * blockDim.x + threadIdx.x;
    if (n >= NN) return;
    int s = g_OFF[n], t = g_OFF[n + 1];
    for (int i = s + 1; i < t; i++) {
        int v = g_BKT[i];
        int j = i - 1;
        while (j >= s && g_BKT[j] > v) { g_BKT[j + 1] = g_BKT[j]; j--; }
        g_BKT[j + 1] = v;
    }
}

// ---------------- per-node gather (streaming, 4x unrolled) ----------------
__global__ void __launch_bounds__(256) gather_kernel(
    const float* __restrict__ alpha, const float* __restrict__ beta)
{
    __shared__ float red[256];
    int n = blockIdx.x;
    int j = threadIdx.x;
    int s = g_OFF[n], t = g_OFF[n + 1];
    float as = 0.f, av0 = 0.f, av1 = 0.f, av2 = 0.f;

    int jl = j & 127;
    bool spart = (j < 128);
    const float* xvbase = g_UV + jl * 3;

    int i = s;
    for (; i + 3 < t; i += 4) {
        int snd_[4];
        float4 y_[4];
        const __half* tp_[4];
        #pragma unroll
        for (int q = 0; q < 4; q++) {
            snd_[q] = g_PSND[i + q];
            y_[q] = g_PEA[i + q];
            tp_[q] = g_TPWh + (size_t)(i + q) * 512;
        }
        if (spart) {
            float w1_[4], w2_[4], xs_[4];
            #pragma unroll
            for (int q = 0; q < 4; q++) {
                w1_[q] = __half2float(tp_[q][jl]);
                w2_[q] = __half2float(tp_[q][128 + jl]);
                xs_[q] = g_US[snd_[q] * 128 + jl];
            }
            #pragma unroll
            for (int q = 0; q < 4; q++) {
                as = fmaf(w1_[q] * xs_[q], y_[q].x, as);
                float t2 = w2_[q] * xs_[q] * IS3;
                av0 = fmaf(t2, y_[q].y, av0);
                av1 = fmaf(t2, y_[q].z, av1);
                av2 = fmaf(t2, y_[q].w, av2);
            }
        } else {
            float w3_[4], w4_[4];
            float x0_[4], x1_[4], x2_[4];
            #pragma unroll
            for (int q = 0; q < 4; q++) {
                w3_[q] = __half2float(tp_[q][256 + jl]);
                w4_[q] = __half2float(tp_[q][384 + jl]);
                const float* xv = xvbase + snd_[q] * 384;
                x0_[q] = xv[0]; x1_[q] = xv[1]; x2_[q] = xv[2];
            }
            #pragma unroll
            for (int q = 0; q < 4; q++) {
                float sv = x0_[q] * y_[q].y + x1_[q] * y_[q].z + x2_[q] * y_[q].w;
                as = fmaf(w4_[q] * IS3, sv, as);
                float t3 = w3_[q] * y_[q].x * IS3;
                av0 = fmaf(t3, x0_[q], av0);
                av1 = fmaf(t3, x1_[q], av1);
                av2 = fmaf(t3, x2_[q], av2);
            }
        }
    }
    for (; i < t; i++) {
        int snd = g_PSND[i];
        float4 y = g_PEA[i];
        const __half* tp = g_TPWh + (size_t)i * 512;
        if (spart) {
            float w1 = __half2float(tp[jl]);
            float w2 = __half2float(tp[128 + jl]);
            float xs = g_US[snd * 128 + jl];
            as = fmaf(w1 * xs, y.x, as);
            float t2 = w2 * xs * IS3;
            av0 = fmaf(t2, y.y, av0);
            av1 = fmaf(t2, y.z, av1);
            av2 = fmaf(t2, y.w, av2);
        } else {
            float w3 = __half2float(tp[256 + jl]);
            float w4 = __half2float(tp[384 + jl]);
            const float* xv = xvbase + snd * 384;
            float x0 = xv[0], x1 = xv[1], x2 = xv[2];
            float sv = x0 * y.y + x1 * y.z + x2 * y.w;
            as = fmaf(w4 * IS3, sv, as);
            float t3 = w3 * y.x * IS3;
            av0 = fmaf(t3, x0, av0);
            av1 = fmaf(t3, x1, av1);
            av2 = fmaf(t3, x2, av2);
        }
    }
    float dsum = 0.f;
    for (int q = s + j; q < t; q += 256) dsum += g_ED[q];
    red[j] = dsum;
    __syncthreads();
    for (int o = 128; o > 0; o >>= 1) {
        if (j < o) red[j] += red[j + o];
        __syncthreads();
    }
    float invd = 1.f / (red[0] * beta[0] + alpha[0]);

    g_MSGS[n * 256 + j] = as * invd;
    g_MSGV[n * 768 + j * 3 + 0] = av0 * invd;
    g_MSGV[n * 768 + j * 3 + 1] = av1 * invd;
    g_MSGV[n * 768 + j * 3 + 2] = av2 * invd;
}

// ---------------- host ----------------
static float* sym(const void* symbol) {
    void* p = nullptr;
    cudaGetSymbolAddress(&p, symbol);
    return (float*)p;
}

extern "C" void kernel_launch(void* const* d_in, const int* in_sizes, int n_in,
                              void* d_out, int out_size)
{
    const float* node_attrs = (const float*)d_in[0];
    const float* node_feats = (const float*)d_in[1];
    const float* edge_attrs = (const float*)d_in[2];
    const float* edge_feats = (const float*)d_in[3];
    const int*   ei         = (const int*)  d_in[4];
    const float* W_skip_s = (const float*)d_in[5];
    const float* W_skip_v = (const float*)d_in[6];
    const float* W_up_s   = (const float*)d_in[7];
    const float* W_up_v   = (const float*)d_in[8];
    const float* W_src    = (const float*)d_in[9];
    const float* W_tgt    = (const float*)d_in[10];
    const float* W_r0     = (const float*)d_in[11];
    const float* W_r1     = (const float*)d_in[12];
    const float* W_r2     = (const float*)d_in[13];
    const float* W_r3     = (const float*)d_in[14];
    const float* W_d0     = (const float*)d_in[15];
    const float* W_d1     = (const float*)d_in[16];
    const float* W1_s     = (const float*)d_in[17];
    const float* W1_v     = (const float*)d_in[18];
    const float* Wres_s   = (const float*)d_in[19];
    const float* Wres_v   = (const float*)d_in[20];
    const float* W2_s     = (const float*)d_in[21];
    const float* W2_v     = (const float*)d_in[22];
    const float* alpha    = (const float*)d_in[23];
    const float* beta     = (const float*)d_in[24];

    float* out    = (float*)d_out;
    float* out_sc = (float*)d_out + (size_t)NN * 512;

    float* US   = sym(g_US);   float* UV   = sym(g_UV);
    float* ABCD = sym(g_ABCD);
    float* MSGS = sym(g_MSGS); float* MSGV = sym(g_MSGV);
    float* MS   = sym(g_MS);   float* MV   = sym(g_MV);
    float* Wns  = sym(g_Wns);  float* Wnv  = sym(g_Wnv);
    float* Wc   = sym(g_Wc);
    float* Wms  = sym(g_Wms);  float* Wmv  = sym(g_Wmv);

    cudaFuncSetAttribute(mma_gemm_kernel,
                         cudaFuncAttributeMaxDynamicSharedMemorySize, MMA_SMEM);
    cudaFuncSetAttribute(outs_gemm_kernel,
                         cudaFuncAttributeMaxDynamicSharedMemorySize, MMA_SMEM);
    cudaFuncSetAttribute(outv_gemm_kernel,
                         cudaFuncAttributeMaxDynamicSharedMemorySize, MMA_SMEM);
    cudaFuncSetAttribute(edge_mlp_kernel,
                         cudaFuncAttributeMaxDynamicSharedMemorySize, EDGE_SMEM);

    // side stream + fork/join events (created once; capture forks/joins via events)
    static cudaStream_t s_side = nullptr;
    static cudaEvent_t  s_ev[6] = {};
    if (s_side == nullptr) {
        cudaStreamCreateWithFlags(&s_side, cudaStreamNonBlocking);
        for (int i = 0; i < 6; i++)
            cudaEventCreateWithFlags(&s_ev[i], cudaEventDisableTiming);
    }

    dim3 B(256);
    const int BIG = 1 << 30;

    prep_kernel<<<384, B>>>(W_skip_s, W_skip_v, W_up_s, W_up_v, W_src, W_tgt,
                            W_r0, W_d0, W_r1, W_r2, W_r3,
                            W1_s, W1_v, Wres_s, Wres_v);

    // fork 1: bucketing chain + ABCD GEMM on side; node GEMMs on main
    cudaEventRecord(s_ev[0], 0);
    cudaStreamWaitEvent(s_side, s_ev[0], 0);

    count_kernel<<<EE / 256, B, 0, s_side>>>(ei);
    scan_kernel<<<1, 1024, 0, s_side>>>();
    fill_kernel<<<EE / 256, B, 0, s_side>>>(ei);
    sort_kernel<<<NN / 256, B, 0, s_side>>>();
    mma_gemm_kernel<<<dim3(4, 64), B, MMA_SMEM, s_side>>>(
        node_attrs, 10, 1, 0, nullptr, 0, 0, 0, BIG,
        Wc, 256, ABCD, 256, 1, 0, nullptr, 0, 0, 0, BIG, 10, 1.f);
    cudaEventRecord(s_ev[1], s_side);

    mma_gemm_kernel<<<dim3(4, 64), B, MMA_SMEM>>>(
        node_feats, 512, 1, 0, nullptr, 0, 0, 0, BIG,
        Wns, 256, out_sc, 512, 1, 0, US, 128, 1, 0, 128, 128, RS128);
    mma_gemm_kernel<<<dim3(4, 64, 3), B, MMA_SMEM>>>(
        node_feats + 128, 512, 3, 1, nullptr, 0, 0, 0, BIG,
        Wnv, 256, out_sc + 128, 512, 3, 1, UV, 384, 3, 1, 128, 128, RS128);

    // join 1: edge_mlp needs both branches
    cudaStreamWaitEvent(0, s_ev[1], 0);

    edge_mlp_kernel<<<EE / 128, B, EDGE_SMEM>>>(ei, edge_attrs, edge_feats, W_d1);

    gather_kernel<<<NN, B>>>(alpha, beta);

    // fork 2: MV on side; MS then f_s on main; f_v on side after MS done
    cudaEventRecord(s_ev[2], 0);
    cudaStreamWaitEvent(s_side, s_ev[2], 0);
    mma_gemm_kernel<<<dim3(2, 64, 3), B, MMA_SMEM, s_side>>>(
        MSGV, 768, 3, 1, UV, 384, 3, 1, 256,
        Wmv, 128, MV, 384, 3, 1, nullptr, 0, 0, 0, BIG, 384, 1.f);

    mma_gemm_kernel<<<dim3(4, 64), B, MMA_SMEM>>>(
        MSGS, 256, 1, 0, US, 128, 1, 0, 256,
        Wms, 256, MS, 256, 1, 0, nullptr, 0, 0, 0, BIG, 384, 1.f);
    cudaEventRecord(s_ev[3], 0);                 // MS ready

    cudaStreamWaitEvent(s_side, s_ev[3], 0);     // f_v needs MS (gate) + MV
    outv_gemm_kernel<<<dim3(2, 64, 3), B, MMA_SMEM, s_side>>>(W2_v, out);
    cudaEventRecord(s_ev[4], s_side);

    outs_gemm_kernel<<<dim3(2, 64), B, MMA_SMEM>>>(W2_s, out);  // f_s needs MS only

    // final join
    cudaStreamWaitEvent(0, s_ev[4], 0);
}

// round 15
// speedup vs baseline: 1.0004x; 1.0004x over previous
#include <cuda_runtime.h>
#include <cuda_bf16.h>
#include <cuda_fp16.h>
#include <cstdint>

#define NN 8192
#define EE 131072
#define IS3 0.5773502691896258f

// ---------------- static scratch ----------------
__device__ float g_US[NN*128];
__device__ float g_UV[NN*384];
__device__ float g_ABCD[NN*256];          // AS|AT|BS|BT
__device__ __half g_TPWh[(size_t)EE*512]; // position-ordered, fp16
__device__ float g_ED[EE];                // position-ordered
__device__ int   g_PSND[EE];              // position-ordered sender
__device__ float4 g_PEA[EE];              // position-ordered edge_attrs
__device__ float g_MSGS[NN*256];
__device__ float g_MSGV[NN*768];
__device__ float g_MS[NN*256];
__device__ float g_MV[NN*384];
__device__ int   g_CNT[NN];
__device__ int   g_OFF[NN+1];
__device__ int   g_CUR[NN];
__device__ int   g_BKT[EE];
// packed weights
__device__ float g_Wns[128*256];
__device__ float g_Wnv[128*256];
__device__ float g_Wc[10*256];
__device__ float g_Wt8[8*128];
__device__ float g_Wms[384*256];
__device__ float g_Wmv[384*128];
__device__ uint32_t g_Wr1t[64*64];        // pre-rounded tf32 bits
__device__ uint32_t g_Wr2t[64*64];
__device__ uint32_t g_Wr3t[64*512];

#define RS128 0.08838834764831845f
#define RS10  0.31622776601683794f
#define RS64  0.125f
#define RS256 0.0625f
#define RS264 0.061545745489666336f

// ---------------- tf32 helpers ----------------
__device__ __forceinline__ uint32_t f2tf(float x) {
    uint32_t u;
    asm("cvt.rna.tf32.f32 %0, %1;" : "=r"(u) : "f"(x));
    return u;
}
__device__ __forceinline__ void mma_tf32(float* c, const uint32_t* a, uint32_t b0, uint32_t b1) {
    asm volatile(
        "mma.sync.aligned.m16n8k8.row.col.f32.tf32.tf32.f32 "
        "{%0,%1,%2,%3}, {%4,%5,%6,%7}, {%8,%9}, {%0,%1,%2,%3};"
        : "+f"(c[0]), "+f"(c[1]), "+f"(c[2]), "+f"(c[3])
        : "r"(a[0]), "r"(a[1]), "r"(a[2]), "r"(a[3]), "r"(b0), "r"(b1));
}
__device__ __forceinline__ float siluf(float x) { return x / (1.f + __expf(-x)); }
__device__ __forceinline__ float sigmf(float x) { return 1.f / (1.f + __expf(-x)); }

#define AP 68
#define BP 72
#define MMA_SMEM ((128*AP + 64*BP) * 4)
#define EDGE_SMEM (MMA_SMEM + (64 + 384 + 1024 + 1024) * 4)

__device__ __forceinline__ void tile_mma64(
    const uint32_t* __restrict__ As, const uint32_t* __restrict__ Bs,
    int wr, int wc, int g, int l, float acc[2][4][4])
{
    #pragma unroll
    for (int kt = 0; kt < 8; kt++) {
        uint32_t a[2][4];
        #pragma unroll
        for (int mt = 0; mt < 2; mt++) {
            int base = (wr * 32 + mt * 16 + g) * AP + kt * 8 + l;
            a[mt][0] = As[base];
            a[mt][1] = As[base + 8 * AP];
            a[mt][2] = As[base + 4];
            a[mt][3] = As[base + 8 * AP + 4];
        }
        #pragma unroll
        for (int nt = 0; nt < 4; nt++) {
            int bcol = wc * 32 + nt * 8 + g;
            uint32_t b0 = Bs[(kt * 8 + l) * BP + bcol];
            uint32_t b1 = Bs[(kt * 8 + l + 4) * BP + bcol];
            mma_tf32(acc[0][nt], a[0], b0, b1);
            mma_tf32(acc[1][nt], a[1], b0, b1);
        }
    }
}

// ---------------- unified strided/split GEMM ----------------
__global__ void __launch_bounds__(256) mma_gemm_kernel(
    const float* __restrict__ X1, int ldx1, int sx1, int zx1,
    const float* __restrict__ X2, int ldx2, int sx2, int zx2, int K1,
    const float* __restrict__ W, int wld,
    float* __restrict__ Y1, int ldy1, int sy1, int zy1,
    float* __restrict__ Y2, int ldy2, int sy2, int zy2, int N1,
    int K, float scale)
{
    extern __shared__ uint32_t smem[];
    uint32_t* As = smem;
    uint32_t* Bs = smem + 128 * AP;

    int t  = threadIdx.x;
    int r0 = blockIdx.y * 128;
    int c0 = blockIdx.x * 64;
    int z  = blockIdx.z;

    int warp = t >> 5, lane = t & 31;
    int wr = warp >> 1, wc = warp & 1;
    int g = lane >> 2, l = lane & 3;

    float acc[2][4][4] = {};

    for (int k0 = 0; k0 < K; k0 += 64) {
        const float* Xp; int ld, sxx, kb;
        if (k0 < K1) { Xp = X1 + (size_t)z * zx1; ld = ldx1; sxx = sx1; kb = k0; }
        else         { Xp = X2 + (size_t)z * zx2; ld = ldx2; sxx = sx2; kb = k0 - K1; }
        int rem = K - k0;

        if (sxx == 1 && rem >= 64) {
            #pragma unroll
            for (int i = 0; i < 8; i++) {
                int e = t + i * 256;
                int row = e >> 4, c4 = (e & 15) * 4;
                float4 v = *reinterpret_cast<const float4*>(
                    &Xp[(size_t)(r0 + row) * ld + kb + c4]);
                uint4 u = make_uint4(f2tf(v.x), f2tf(v.y), f2tf(v.z), f2tf(v.w));
                *reinterpret_cast<uint4*>(&As[row * AP + c4]) = u;
            }
        } else {
            #pragma unroll
            for (int i = 0; i < 32; i++) {
                int e = t + i * 256;
                int row = e >> 6, col = e & 63;
                float x = (col < rem) ? Xp[(size_t)(r0 + row) * ld + (size_t)(kb + col) * sxx] : 0.f;
                As[row * AP + col] = f2tf(x);
            }
        }
        #pragma unroll
        for (int i = 0; i < 4; i++) {
            int e = t + i * 256;
            int row = e >> 4, c4 = (e & 15) * 4;
            int kk = k0 + row;
            float4 v = make_float4(0.f, 0.f, 0.f, 0.f);
            if (kk < K)
                v = *reinterpret_cast<const float4*>(&W[(size_t)kk * wld + c0 + c4]);
            uint4 u = make_uint4(f2tf(v.x), f2tf(v.y), f2tf(v.z), f2tf(v.w));
            *reinterpret_cast<uint4*>(&Bs[row * BP + c4]) = u;
        }
        __syncthreads();
        tile_mma64(As, Bs, wr, wc, g, l, acc);
        __syncthreads();
    }

    float* Yp; int ldy, syy; int colb;
    if (Y2 != nullptr && c0 >= N1) {
        Yp = Y2 + (size_t)z * zy2; ldy = ldy2; syy = sy2; colb = c0 - N1;
    } else {
        Yp = Y1 + (size_t)z * zy1; ldy = ldy1; syy = sy1; colb = c0;
    }

    #pragma unroll
    for (int mt = 0; mt < 2; mt++)
        #pragma unroll
        for (int idx = 0; idx < 4; idx++) {
            int row = r0 + wr * 32 + mt * 16 + g + ((idx >= 2) ? 8 : 0);
            #pragma unroll
            for (int nt = 0; nt < 4; nt++) {
                int col = colb + wc * 32 + nt * 8 + 2 * l + (idx & 1);
                Yp[(size_t)row * ldy + (size_t)col * syy] = acc[mt][nt][idx] * scale;
            }
        }
}

// ---------------- output GEMMs with fused activations ----------------
// f_s = silu(MS[:, :128]) @ W2_s * RS128 -> out[:, :, 0]
__global__ void __launch_bounds__(256) outs_gemm_kernel(
    const float* __restrict__ W2_s, float* __restrict__ out)
{
    extern __shared__ uint32_t smem[];
    uint32_t* As = smem;
    uint32_t* Bs = smem + 128 * AP;

    int t  = threadIdx.x;
    int r0 = blockIdx.y * 128;
    int c0 = blockIdx.x * 64;
    int warp = t >> 5, lane = t & 31;
    int wr = warp >> 1, wc = warp & 1;
    int g = lane >> 2, l = lane & 3;

    float acc[2][4][4] = {};

    #pragma unroll
    for (int k0 = 0; k0 < 128; k0 += 64) {
        #pragma unroll
        for (int i = 0; i < 8; i++) {
            int e = t + i * 256;
            int row = e >> 4, c4 = (e & 15) * 4;
            float4 v = *reinterpret_cast<const float4*>(
                &g_MS[(size_t)(r0 + row) * 256 + k0 + c4]);
            uint4 u = make_uint4(f2tf(siluf(v.x)), f2tf(siluf(v.y)),
                                 f2tf(siluf(v.z)), f2tf(siluf(v.w)));
            *reinterpret_cast<uint4*>(&As[row * AP + c4]) = u;
        }
        #pragma unroll
        for (int i = 0; i < 4; i++) {
            int e = t + i * 256;
            int row = e >> 4, c4 = (e & 15) * 4;
            float4 v = *reinterpret_cast<const float4*>(
                &W2_s[(size_t)(k0 + row) * 128 + c0 + c4]);
            uint4 u = make_uint4(f2tf(v.x), f2tf(v.y), f2tf(v.z), f2tf(v.w));
            *reinterpret_cast<uint4*>(&Bs[row * BP + c4]) = u;
        }
        __syncthreads();
        tile_mma64(As, Bs, wr, wc, g, l, acc);
        __syncthreads();
    }

    #pragma unroll
    for (int mt = 0; mt < 2; mt++)
        #pragma unroll
        for (int idx = 0; idx < 4; idx++) {
            int row = r0 + wr * 32 + mt * 16 + g + ((idx >= 2) ? 8 : 0);
            #pragma unroll
            for (int nt = 0; nt < 4; nt++) {
                int col = c0 + wc * 32 + nt * 8 + 2 * l + (idx & 1);
                out[(size_t)row * 512 + col * 4] = acc[mt][nt][idx] * RS128;
            }
        }
}

// f_v[cc] = (MV[:, :, cc] * sigmoid(MS[:, 128:])) @ W2_v * RS128 -> out[:, :, 1+cc]
__global__ void __launch_bounds__(256) outv_gemm_kernel(
    const float* __restrict__ W2_v, float* __restrict__ out)
{
    extern __shared__ uint32_t smem[];
    uint32_t* As = smem;
    uint32_t* Bs = smem + 128 * AP;

    int t  = threadIdx.x;
    int r0 = blockIdx.y * 128;
    int c0 = blockIdx.x * 64;
    int cc = blockIdx.z;
    int warp = t >> 5, lane = t & 31;
    int wr = warp >> 1, wc = warp & 1;
    int g = lane >> 2, l = lane & 3;

    float acc[2][4][4] = {};

    #pragma unroll
    for (int k0 = 0; k0 < 128; k0 += 64) {
        #pragma unroll
        for (int i = 0; i < 32; i++) {
            int e = t + i * 256;
            int row = e >> 6, col = e & 63;
            int rr = r0 + row, k = k0 + col;
            float gate = sigmf(g_MS[(size_t)rr * 256 + 128 + k]);
            float x = g_MV[(size_t)rr * 384 + k * 3 + cc] * gate;
            As[row * AP + col] = f2tf(x);
        }
        #pragma unroll
        for (int i = 0; i < 4; i++) {
            int e = t + i * 256;
            int row = e >> 4, c4 = (e & 15) * 4;
            float4 v = *reinterpret_cast<const float4*>(
                &W2_v[(size_t)(k0 + row) * 128 + c0 + c4]);
            uint4 u = make_uint4(f2tf(v.x), f2tf(v.y), f2tf(v.z), f2tf(v.w));
            *reinterpret_cast<uint4*>(&Bs[row * BP + c4]) = u;
        }
        __syncthreads();
        tile_mma64(As, Bs, wr, wc, g, l, acc);
        __syncthreads();
    }

    #pragma unroll
    for (int mt = 0; mt < 2; mt++)
        #pragma unroll
        for (int idx = 0; idx < 4; idx++) {
            int row = r0 + wr * 32 + mt * 16 + g + ((idx >= 2) ? 8 : 0);
            #pragma unroll
            for (int nt = 0; nt < 4; nt++) {
                int col = c0 + wc * 32 + nt * 8 + 2 * l + (idx & 1);
                out[(size_t)row * 512 + col * 4 + 1 + cc] = acc[mt][nt][idx] * RS128;
            }
        }
}

// ---------------- fused edge MLP (bucket-position order) ----------------
__global__ void __launch_bounds__(256) edge_mlp_kernel(
    const int* __restrict__ ei, const float* __restrict__ edge_attrs,
    const float* __restrict__ edge_feats, const float* __restrict__ Wd1)
{
    extern __shared__ uint32_t smem[];
    uint32_t* As = smem;
    uint32_t* Bs = smem + 128 * AP;
    float* sWd1 = (float*)(Bs + 64 * BP);
    int*   sSnd = (int*)(sWd1 + 64);
    int*   sRcv = sSnd + 128;
    int*   sEd  = sRcv + 128;
    float* sEf  = (float*)(sEd + 128);       // [128][8]
    float* sW8  = sEf + 128 * 8;             // [8][128]

    int t = threadIdx.x;
    int e0 = blockIdx.x * 128;               // position base
    int warp = t >> 5, lane = t & 31;
    int wr = warp >> 1, wc = warp & 1;
    int g = lane >> 2, l = lane & 3;

    if (t < 64) sWd1[t] = Wd1[t];
    if (t < 128) {
        int ed = g_BKT[e0 + t];
        sEd[t] = ed;
        int snd = ei[ed];
        sSnd[t] = snd;
        sRcv[t] = ei[EE + ed];
        g_PSND[e0 + t] = snd;
        g_PEA[e0 + t] = reinterpret_cast<const float4*>(edge_attrs)[ed];
    }
    #pragma unroll
    for (int i = 0; i < 4; i++) sW8[t + i * 256] = g_Wt8[t + i * 256];
    __syncthreads();

    // edge_feats rows by gathered index (32B per edge, L2-resident)
    {
        float4 v = *reinterpret_cast<const float4*>(
            &edge_feats[(size_t)sEd[t >> 1] * 8 + (t & 1) * 4]);
        reinterpret_cast<float4*>(sEf)[t] = v;
    }
    __syncthreads();

    // h0 = silu((ef8@W8[:, :64] + AS[snd] + AT[rcv]) * rs264) -> As
    #pragma unroll
    for (int i = 0; i < 32; i++) {
        int e = t + i * 256;
        int row = e >> 6, c = e & 63;
        float accv = 0.f;
        #pragma unroll
        for (int k = 0; k < 8; k++)
            accv = fmaf(sEf[row * 8 + k], sW8[k * 128 + c], accv);
        float h0 = (accv
                  + g_ABCD[(size_t)sSnd[row] * 256 + c]
                  + g_ABCD[(size_t)sRcv[row] * 256 + 64 + c]) * RS264;
        As[row * AP + c] = f2tf(siluf(h0));
    }
    // density head (cols 64..127 of packed W8)
    for (int el = warp; el < 128; el += 8) {
        int snd = sSnd[el], rcv = sRcv[el];
        float sum = 0.f;
        #pragma unroll
        for (int h = 0; h < 2; h++) {
            int c = lane + h * 32;
            float accv = 0.f;
            #pragma unroll
            for (int k = 0; k < 8; k++)
                accv = fmaf(sEf[el * 8 + k], sW8[k * 128 + 64 + c], accv);
            float d0 = (accv
                      + g_ABCD[(size_t)snd * 256 + 128 + c]
                      + g_ABCD[(size_t)rcv * 256 + 192 + c]) * RS264;
            sum += siluf(d0) * sWd1[c];
        }
        #pragma unroll
        for (int o = 16; o > 0; o >>= 1)
            sum += __shfl_down_sync(0xffffffff, sum, o);
        if (lane == 0) {
            float x = sum * RS64;
            g_ED[e0 + el] = tanhf(x * x);
        }
    }
    // W_r1 (pre-rounded tf32 bits: pure 16B copies)
    #pragma unroll
    for (int i = 0; i < 4; i++) {
        int e = t + i * 256;
        int row = e >> 4, c4 = (e & 15) * 4;
        uint4 u = *reinterpret_cast<const uint4*>(&g_Wr1t[row * 64 + c4]);
        *reinterpret_cast<uint4*>(&Bs[row * BP + c4]) = u;
    }
    __syncthreads();

    float acc[2][4][4] = {};
    tile_mma64(As, Bs, wr, wc, g, l, acc);
    __syncthreads();

    #pragma unroll
    for (int mt = 0; mt < 2; mt++)
        #pragma unroll
        for (int idx = 0; idx < 4; idx++) {
            int row = wr * 32 + mt * 16 + g + ((idx >= 2) ? 8 : 0);
            #pragma unroll
            for (int nt = 0; nt < 4; nt++) {
                int col = wc * 32 + nt * 8 + 2 * l + (idx & 1);
                As[row * AP + col] = f2tf(siluf(acc[mt][nt][idx] * RS64));
            }
        }
    #pragma unroll
    for (int i = 0; i < 4; i++) {
        int e = t + i * 256;
        int row = e >> 4, c4 = (e & 15) * 4;
        uint4 u = *reinterpret_cast<const uint4*>(&g_Wr2t[row * 64 + c4]);
        *reinterpret_cast<uint4*>(&Bs[row * BP + c4]) = u;
    }
    __syncthreads();

    float acc2[2][4][4] = {};
    tile_mma64(As, Bs, wr, wc, g, l, acc2);
    __syncthreads();

    #pragma unroll
    for (int mt = 0; mt < 2; mt++)
        #pragma unroll
        for (int idx = 0; idx < 4; idx++) {
            int row = wr * 32 + mt * 16 + g + ((idx >= 2) ? 8 : 0);
            #pragma unroll
            for (int nt = 0; nt < 4; nt++) {
                int col = wc * 32 + nt * 8 + 2 * l + (idx & 1);
                As[row * AP + col] = f2tf(siluf(acc2[mt][nt][idx] * RS64));
            }
        }
    __syncthreads();

    for (int ct = 0; ct < 8; ct++) {
        #pragma unroll
        for (int i = 0; i < 4; i++) {
            int e = t + i * 256;
            int row = e >> 4, c4 = (e & 15) * 4;
            uint4 u = *reinterpret_cast<const uint4*>(&g_Wr3t[row * 512 + ct * 64 + c4]);
            *reinterpret_cast<uint4*>(&Bs[row * BP + c4]) = u;
        }
        __syncthreads();
        float acc3[2][4][4] = {};
        tile_mma64(As, Bs, wr, wc, g, l, acc3);
        #pragma unroll
        for (int mt = 0; mt < 2; mt++)
            #pragma unroll
            for (int hi = 0; hi < 2; hi++) {
                int row = e0 + wr * 32 + mt * 16 + g + (hi ? 8 : 0);
                #pragma unroll
                for (int nt = 0; nt < 4; nt++) {
                    int col = ct * 64 + wc * 32 + nt * 8 + 2 * l;
                    __half2 h = __floats2half2_rn(acc3[mt][nt][hi * 2] * RS64,
                                                  acc3[mt][nt][hi * 2 + 1] * RS64);
                    *reinterpret_cast<__half2*>(&g_TPWh[(size_t)row * 512 + col]) = h;
                }
            }
        __syncthreads();
    }
}

// ---------------- weight prep (+ CNT zeroing folded in) ----------------
__global__ void __launch_bounds__(256) prep_kernel(
    const float* __restrict__ W_skip_s, const float* __restrict__ W_skip_v,
    const float* __restrict__ W_up_s,   const float* __restrict__ W_up_v,
    const float* __restrict__ W_src,    const float* __restrict__ W_tgt,
    const float* __restrict__ W_r0,     const float* __restrict__ W_d0,
    const float* __restrict__ W_r1,     const float* __restrict__ W_r2,
    const float* __restrict__ W_r3,
    const float* __restrict__ W1_s,     const float* __restrict__ W1_v,
    const float* __restrict__ Wres_s,   const float* __restrict__ Wres_v)
{
    int id = blockIdx.x * 256 + threadIdx.x;
    if (id < NN) g_CNT[id] = 0;
    if (id < 128 * 256) {
        int m = id >> 8, j = id & 255;
        g_Wns[id] = (j < 128) ? W_skip_s[m * 128 + j] : W_up_s[m * 128 + j - 128];
        g_Wnv[id] = (j < 128) ? W_skip_v[m * 128 + j] : W_up_v[m * 128 + j - 128];
    }
    if (id < 8 * 128) {
        int m = id >> 7, j = id & 127;
        g_Wt8[id] = (j < 64) ? W_r0[m * 64 + j] : W_d0[m * 64 + j - 64];
    }
    if (id < 384 * 256) {
        int k = id >> 8, j = id & 255;
        g_Wms[id] = (k < 256) ? W1_s[k * 256 + j] * RS256
                              : Wres_s[(k - 256) * 256 + j] * RS128;
    }
    if (id < 384 * 128) {
        int k = id / 128, j = id % 128;
        g_Wmv[id] = (k < 256) ? W1_v[k * 128 + j] * RS256
                              : Wres_v[(k - 256) * 128 + j] * RS128;
    }
    if (id < 64 * 64) {
        g_Wr1t[id] = f2tf(W_r1[id]);
        g_Wr2t[id] = f2tf(W_r2[id]);
    }
    if (id < 64 * 512) {
        g_Wr3t[id] = f2tf(W_r3[id]);
    }
    if (id < 10 * 256) {
        int a = id >> 8, j = id & 255;
        int q = j >> 6, jj = j & 63;
        const float* S = (q == 0 || q == 2) ? W_src : W_tgt;
        const float* M = (q < 2) ? W_r0 : W_d0;
        int off = (q == 0 || q == 2) ? 8 : 136;
        float s = 0.f;
        for (int m = 0; m < 128; m++)
            s += S[a * 128 + m] * M[(off + m) * 64 + jj];
        g_Wc[a * 256 + j] = s * RS10;
    }
}

// ---------------- bucketing ----------------
__global__ void count_kernel(const int* __restrict__ ei) {
    int e = blockIdx.x * blockDim.x + threadIdx.x;
    if (e < EE) atomicAdd(&g_CNT[ei[EE + e]], 1);
}
__global__ void __launch_bounds__(1024) scan_kernel() {
    __shared__ int wt[32];
    int t = threadIdx.x, lane = t & 31, w = t >> 5;
    int base = t * 8;
    int4 lo = reinterpret_cast<const int4*>(g_CNT)[t * 2];
    int4 hi = reinterpret_cast<const int4*>(g_CNT)[t * 2 + 1];
    int local[8] = {lo.x, lo.y, lo.z, lo.w, hi.x, hi.y, hi.z, hi.w};
    int s = 0;
    #pragma unroll
    for (int i = 0; i < 8; i++) s += local[i];
    int v = s;
    #pragma unroll
    for (int o = 1; o < 32; o <<= 1) {
        int u = __shfl_up_sync(0xffffffff, v, o);
        if (lane >= o) v += u;
    }
    if (lane == 31) wt[w] = v;
    __syncthreads();
    if (w == 0) {
        int x = wt[lane];
        #pragma unroll
        for (int o = 1; o < 32; o <<= 1) {
            int u = __shfl_up_sync(0xffffffff, x, o);
            if (lane >= o) x += u;
        }
        wt[lane] = x;
    }
    __syncthreads();
    int run = v - s + (w > 0 ? wt[w - 1] : 0);
    #pragma unroll
    for (int i = 0; i < 8; i++) { g_OFF[base + i] = run; g_CUR[base + i] = run; run += local[i]; }
    if (t == 1023) g_OFF[NN] = run;
}
__global__ void fill_kernel(const int* __restrict__ ei) {
    int e = blockIdx.x * blockDim.x + threadIdx.x;
    if (e < EE) {
        int pos = atomicAdd(&g_CUR[ei[EE + e]], 1);
        g_BKT[pos] = e;
    }
}
__global__ void sort_kernel() {
    int n = blockIdx.x * blockDim.x + threadIdx.x;
    if (n >= NN) return;
    int s = g_OFF[n], t = g_OFF[n + 1];
    for (int i = s + 1; i < t; i++) {
        int v = g_BKT[i];
        int j = i - 1;
        while (j >= s && g_BKT[j] > v) { g_BKT[j + 1] = g_BKT[j]; j--; }
        g_BKT[j + 1] = v;
    }
}

// ---------------- per-node gather (streaming, 2x unrolled) ----------------
__global__ void __launch_bounds__(256) gather_kernel(
    const float* __restrict__ alpha, const float* __restrict__ beta)
{
    __shared__ float red[256];
    int n = blockIdx.x;
    int j = threadIdx.x;
    int s = g_OFF[n], t = g_OFF[n + 1];
    float as = 0.f, av0 = 0.f, av1 = 0.f, av2 = 0.f;

    int jl = j & 127;
    bool spart = (j < 128);
    const float* xvbase = g_UV + jl * 3;

    int i = s;
    for (; i + 1 < t; i += 2) {
        int snd0 = g_PSND[i],     snd1 = g_PSND[i + 1];
        float4 y0 = g_PEA[i],     y1 = g_PEA[i + 1];
        const __half* tp0 = g_TPWh + (size_t)i * 512;
        const __half* tp1 = g_TPWh + (size_t)(i + 1) * 512;
        if (spart) {
            float w1a = __half2float(tp0[jl]),       w1b = __half2float(tp1[jl]);
            float w2a = __half2float(tp0[128 + jl]), w2b = __half2float(tp1[128 + jl]);
            float xsa = g_US[snd0 * 128 + jl],       xsb = g_US[snd1 * 128 + jl];
            as = fmaf(w1a * xsa, y0.x, as);
            float t2a = w2a * xsa * IS3;
            av0 = fmaf(t2a, y0.y, av0);
            av1 = fmaf(t2a, y0.z, av1);
            av2 = fmaf(t2a, y0.w, av2);
            as = fmaf(w1b * xsb, y1.x, as);
            float t2b = w2b * xsb * IS3;
            av0 = fmaf(t2b, y1.y, av0);
            av1 = fmaf(t2b, y1.z, av1);
            av2 = fmaf(t2b, y1.w, av2);
        } else {
            float w3a = __half2float(tp0[256 + jl]), w3b = __half2float(tp1[256 + jl]);
            float w4a = __half2float(tp0[384 + jl]), w4b = __half2float(tp1[384 + jl]);
            const float* xva = xvbase + snd0 * 384;
            const float* xvb = xvbase + snd1 * 384;
            float xa0 = xva[0], xa1 = xva[1], xa2 = xva[2];
            float xb0 = xvb[0], xb1 = xvb[1], xb2 = xvb[2];
            float sva = xa0 * y0.y + xa1 * y0.z + xa2 * y0.w;
            as = fmaf(w4a * IS3, sva, as);
            float t3a = w3a * y0.x * IS3;
            av0 = fmaf(t3a, xa0, av0);
            av1 = fmaf(t3a, xa1, av1);
            av2 = fmaf(t3a, xa2, av2);
            float svb = xb0 * y1.y + xb1 * y1.z + xb2 * y1.w;
            as = fmaf(w4b * IS3, svb, as);
            float t3b = w3b * y1.x * IS3;
            av0 = fmaf(t3b, xb0, av0);
            av1 = fmaf(t3b, xb1, av1);
            av2 = fmaf(t3b, xb2, av2);
        }
    }
    for (; i < t; i++) {
        int snd = g_PSND[i];
        float4 y = g_PEA[i];
        const __half* tp = g_TPWh + (size_t)i * 512;
        if (spart) {
            float w1 = __half2float(tp[jl]);
            float w2 = __half2float(tp[128 + jl]);
            float xs = g_US[snd * 128 + jl];
            as = fmaf(w1 * xs, y.x, as);
            float t2 = w2 * xs * IS3;
            av0 = fmaf(t2, y.y, av0);
            av1 = fmaf(t2, y.z, av1);
            av2 = fmaf(t2, y.w, av2);
        } else {
            float w3 = __half2float(tp[256 + jl]);
            float w4 = __half2float(tp[384 + jl]);
            const float* xv = xvbase + snd * 384;
            float x0 = xv[0], x1 = xv[1], x2 = xv[2];
            float sv = x0 * y.y + x1 * y.z + x2 * y.w;
            as = fmaf(w4 * IS3, sv, as);
            float t3 = w3 * y.x * IS3;
            av0 = fmaf(t3, x0, av0);
            av1 = fmaf(t3, x1, av1);
            av2 = fmaf(t3, x2, av2);
        }
    }
    float dsum = 0.f;
    for (int q = s + j; q < t; q += 256) dsum += g_ED[q];
    red[j] = dsum;
    __syncthreads();
    for (int o = 128; o > 0; o >>= 1) {
        if (j < o) red[j] += red[j + o];
        __syncthreads();
    }
    float invd = 1.f / (red[0] * beta[0] + alpha[0]);

    g_MSGS[n * 256 + j] = as * invd;
    g_MSGV[n * 768 + j * 3 + 0] = av0 * invd;
    g_MSGV[n * 768 + j * 3 + 1] = av1 * invd;
    g_MSGV[n * 768 + j * 3 + 2] = av2 * invd;
}

// ---------------- host ----------------
static float* sym(const void* symbol) {
    void* p = nullptr;
    cudaGetSymbolAddress(&p, symbol);
    return (float*)p;
}

extern "C" void kernel_launch(void* const* d_in, const int* in_sizes, int n_in,
                              void* d_out, int out_size)
{
    const float* node_attrs = (const float*)d_in[0];
    const float* node_feats = (const float*)d_in[1];
    const float* edge_attrs = (const float*)d_in[2];
    const float* edge_feats = (const float*)d_in[3];
    const int*   ei         = (const int*)  d_in[4];
    const float* W_skip_s = (const float*)d_in[5];
    const float* W_skip_v = (const float*)d_in[6];
    const float* W_up_s   = (const float*)d_in[7];
    const float* W_up_v   = (const float*)d_in[8];
    const float* W_src    = (const float*)d_in[9];
    const float* W_tgt    = (const float*)d_in[10];
    const float* W_r0     = (const float*)d_in[11];
    const float* W_r1     = (const float*)d_in[12];
    const float* W_r2     = (const float*)d_in[13];
    const float* W_r3     = (const float*)d_in[14];
    const float* W_d0     = (const float*)d_in[15];
    const float* W_d1     = (const float*)d_in[16];
    const float* W1_s     = (const float*)d_in[17];
    const float* W1_v     = (const float*)d_in[18];
    const float* Wres_s   = (const float*)d_in[19];
    const float* Wres_v   = (const float*)d_in[20];
    const float* W2_s     = (const float*)d_in[21];
    const float* W2_v     = (const float*)d_in[22];
    const float* alpha    = (const float*)d_in[23];
    const float* beta     = (const float*)d_in[24];

    float* out    = (float*)d_out;
    float* out_sc = (float*)d_out + (size_t)NN * 512;

    float* US   = sym(g_US);   float* UV   = sym(g_UV);
    float* ABCD = sym(g_ABCD);
    float* MSGS = sym(g_MSGS); float* MSGV = sym(g_MSGV);
    float* MS   = sym(g_MS);   float* MV   = sym(g_MV);
    float* Wns  = sym(g_Wns);  float* Wnv  = sym(g_Wnv);
    float* Wc   = sym(g_Wc);
    float* Wms  = sym(g_Wms);  float* Wmv  = sym(g_Wmv);

    cudaFuncSetAttribute(mma_gemm_kernel,
                         cudaFuncAttributeMaxDynamicSharedMemorySize, MMA_SMEM);
    cudaFuncSetAttribute(outs_gemm_kernel,
                         cudaFuncAttributeMaxDynamicSharedMemorySize, MMA_SMEM);
    cudaFuncSetAttribute(outv_gemm_kernel,
                         cudaFuncAttributeMaxDynamicSharedMemorySize, MMA_SMEM);
    cudaFuncSetAttribute(edge_mlp_kernel,
                         cudaFuncAttributeMaxDynamicSharedMemorySize, EDGE_SMEM);

    // side stream + fork/join events (created once; capture forks/joins via events)
    static cudaStream_t s_side = nullptr;
    static cudaEvent_t  s_ev[6] = {};
    if (s_side == nullptr) {
        cudaStreamCreateWithFlags(&s_side, cudaStreamNonBlocking);
        for (int i = 0; i < 6; i++)
            cudaEventCreateWithFlags(&s_ev[i], cudaEventDisableTiming);
    }

    dim3 B(256);
    const int BIG = 1 << 30;

    prep_kernel<<<384, B>>>(W_skip_s, W_skip_v, W_up_s, W_up_v, W_src, W_tgt,
                            W_r0, W_d0, W_r1, W_r2, W_r3,
                            W1_s, W1_v, Wres_s, Wres_v);

    // fork 1: bucketing chain + ABCD GEMM on side; node GEMMs on main
    cudaEventRecord(s_ev[0], 0);
    cudaStreamWaitEvent(s_side, s_ev[0], 0);

    count_kernel<<<EE / 256, B, 0, s_side>>>(ei);
    scan_kernel<<<1, 1024, 0, s_side>>>();
    fill_kernel<<<EE / 256, B, 0, s_side>>>(ei);
    sort_kernel<<<NN / 256, B, 0, s_side>>>();
    mma_gemm_kernel<<<dim3(4, 64), B, MMA_SMEM, s_side>>>(
        node_attrs, 10, 1, 0, nullptr, 0, 0, 0, BIG,
        Wc, 256, ABCD, 256, 1, 0, nullptr, 0, 0, 0, BIG, 10, 1.f);
    cudaEventRecord(s_ev[1], s_side);

    mma_gemm_kernel<<<dim3(4, 64), B, MMA_SMEM>>>(
        node_feats, 512, 1, 0, nullptr, 0, 0, 0, BIG,
        Wns, 256, out_sc, 512, 1, 0, US, 128, 1, 0, 128, 128, RS128);
    mma_gemm_kernel<<<dim3(4, 64, 3), B, MMA_SMEM>>>(
        node_feats + 128, 512, 3, 1, nullptr, 0, 0, 0, BIG,
        Wnv, 256, out_sc + 128, 512, 3, 1, UV, 384, 3, 1, 128, 128, RS128);

    // join 1: edge_mlp needs both branches
    cudaStreamWaitEvent(0, s_ev[1], 0);

    edge_mlp_kernel<<<EE / 128, B, EDGE_SMEM>>>(ei, edge_attrs, edge_feats, W_d1);

    gather_kernel<<<NN, B>>>(alpha, beta);

    // fork 2: MV on side; MS then f_s on main; f_v on side after MS done
    cudaEventRecord(s_ev[2], 0);
    cudaStreamWaitEvent(s_side, s_ev[2], 0);
    mma_gemm_kernel<<<dim3(2, 64, 3), B, MMA_SMEM, s_side>>>(
        MSGV, 768, 3, 1, UV, 384, 3, 1, 256,
        Wmv, 128, MV, 384, 3, 1, nullptr, 0, 0, 0, BIG, 384, 1.f);

    mma_gemm_kernel<<<dim3(4, 64), B, MMA_SMEM>>>(
        MSGS, 256, 1, 0, US, 128, 1, 0, 256,
        Wms, 256, MS, 256, 1, 0, nullptr, 0, 0, 0, BIG, 384, 1.f);
    cudaEventRecord(s_ev[3], 0);                 // MS ready

    cudaStreamWaitEvent(s_side, s_ev[3], 0);     // f_v needs MS (gate) + MV
    outv_gemm_kernel<<<dim3(2, 64, 3), B, MMA_SMEM, s_side>>>(W2_v, out);
    cudaEventRecord(s_ev[4], s_side);

    outs_gemm_kernel<<<dim3(2, 64), B, MMA_SMEM>>>(W2_s, out);  // f_s needs MS only

    // final join
    cudaStreamWaitEvent(0, s_ev[4], 0);
}

// round 16
// speedup vs baseline: 1.0980x; 1.0975x over previous
#include <cuda_runtime.h>
#include <cuda_bf16.h>
#include <cuda_fp16.h>
#include <cstdint>

#define NN 8192
#define EE 131072
#define IS3 0.5773502691896258f

// ---------------- static scratch ----------------
__device__ float g_US[NN*128];
__device__ float g_UV[NN*384];
__device__ float g_ABCD[NN*256];          // AS|AT|BS|BT
__device__ __half g_TPWh[(size_t)EE*512]; // position-ordered, fp16
__device__ float g_ED[EE];                // position-ordered
__device__ int   g_PSND[EE];              // position-ordered sender
__device__ float4 g_PEA[EE];              // position-ordered edge_attrs
__device__ float g_MSGS[NN*256];
__device__ float g_MSGV[NN*768];
__device__ float g_MS[NN*256];
__device__ float g_MV[NN*384];
__device__ float g_OS[NN*128];
__device__ float g_OV[NN*384];
__device__ int   g_CNT[NN];
__device__ int   g_OFF[NN+1];
__device__ int   g_CUR[NN];
__device__ int   g_BKT[EE];
// packed weights
__device__ float g_Wns[128*256];
__device__ float g_Wnv[128*256];
__device__ float g_Wc[10*256];
__device__ float g_Wt8[8*128];
__device__ float g_Wms[384*256];
__device__ float g_Wmv[384*128];
__device__ uint32_t g_Wr1t[64*64];        // pre-rounded tf32 bits
__device__ uint32_t g_Wr2t[64*64];
__device__ uint32_t g_Wr3t[64*512];

#define RS128 0.08838834764831845f
#define RS10  0.31622776601683794f
#define RS64  0.125f
#define RS256 0.0625f
#define RS264 0.061545745489666336f

// ---------------- tf32 helpers ----------------
__device__ __forceinline__ uint32_t f2tf(float x) {
    uint32_t u;
    asm("cvt.rna.tf32.f32 %0, %1;" : "=r"(u) : "f"(x));
    return u;
}
__device__ __forceinline__ void mma_tf32(float* c, const uint32_t* a, uint32_t b0, uint32_t b1) {
    asm volatile(
        "mma.sync.aligned.m16n8k8.row.col.f32.tf32.tf32.f32 "
        "{%0,%1,%2,%3}, {%4,%5,%6,%7}, {%8,%9}, {%0,%1,%2,%3};"
        : "+f"(c[0]), "+f"(c[1]), "+f"(c[2]), "+f"(c[3])
        : "r"(a[0]), "r"(a[1]), "r"(a[2]), "r"(a[3]), "r"(b0), "r"(b1));
}
__device__ __forceinline__ float siluf(float x) { return x / (1.f + __expf(-x)); }

#define AP 68
#define BP 72
#define MMA_SMEM ((128*AP + 64*BP) * 4)
#define EDGE_SMEM (MMA_SMEM + (64 + 384 + 1024 + 1024) * 4)

__device__ __forceinline__ void tile_mma64(
    const uint32_t* __restrict__ As, const uint32_t* __restrict__ Bs,
    int wr, int wc, int g, int l, float acc[2][4][4])
{
    #pragma unroll
    for (int kt = 0; kt < 8; kt++) {
        uint32_t a[2][4];
        #pragma unroll
        for (int mt = 0; mt < 2; mt++) {
            int base = (wr * 32 + mt * 16 + g) * AP + kt * 8 + l;
            a[mt][0] = As[base];
            a[mt][1] = As[base + 8 * AP];
            a[mt][2] = As[base + 4];
            a[mt][3] = As[base + 8 * AP + 4];
        }
        #pragma unroll
        for (int nt = 0; nt < 4; nt++) {
            int bcol = wc * 32 + nt * 8 + g;
            uint32_t b0 = Bs[(kt * 8 + l) * BP + bcol];
            uint32_t b1 = Bs[(kt * 8 + l + 4) * BP + bcol];
            mma_tf32(acc[0][nt], a[0], b0, b1);
            mma_tf32(acc[1][nt], a[1], b0, b1);
        }
    }
}

// ---------------- unified strided/split GEMM ----------------
__global__ void __launch_bounds__(256) mma_gemm_kernel(
    const float* __restrict__ X1, int ldx1, int sx1, int zx1,
    const float* __restrict__ X2, int ldx2, int sx2, int zx2, int K1,
    const float* __restrict__ W, int wld,
    float* __restrict__ Y1, int ldy1, int sy1, int zy1,
    float* __restrict__ Y2, int ldy2, int sy2, int zy2, int N1,
    int K, float scale)
{
    extern __shared__ uint32_t smem[];
    uint32_t* As = smem;
    uint32_t* Bs = smem + 128 * AP;

    int t  = threadIdx.x;
    int r0 = blockIdx.y * 128;
    int c0 = blockIdx.x * 64;
    int z  = blockIdx.z;

    int warp = t >> 5, lane = t & 31;
    int wr = warp >> 1, wc = warp & 1;
    int g = lane >> 2, l = lane & 3;

    float acc[2][4][4] = {};

    for (int k0 = 0; k0 < K; k0 += 64) {
        const float* Xp; int ld, sxx, kb;
        if (k0 < K1) { Xp = X1 + (size_t)z * zx1; ld = ldx1; sxx = sx1; kb = k0; }
        else         { Xp = X2 + (size_t)z * zx2; ld = ldx2; sxx = sx2; kb = k0 - K1; }
        int rem = K - k0;

        if (sxx == 1 && rem >= 64) {
            #pragma unroll
            for (int i = 0; i < 8; i++) {
                int e = t + i * 256;
                int row = e >> 4, c4 = (e & 15) * 4;
                float4 v = *reinterpret_cast<const float4*>(
                    &Xp[(size_t)(r0 + row) * ld + kb + c4]);
                uint4 u = make_uint4(f2tf(v.x), f2tf(v.y), f2tf(v.z), f2tf(v.w));
                *reinterpret_cast<uint4*>(&As[row * AP + c4]) = u;
            }
        } else {
            #pragma unroll
            for (int i = 0; i < 32; i++) {
                int e = t + i * 256;
                int row = e >> 6, col = e & 63;
                float x = (col < rem) ? Xp[(size_t)(r0 + row) * ld + (size_t)(kb + col) * sxx] : 0.f;
                As[row * AP + col] = f2tf(x);
            }
        }
        #pragma unroll
        for (int i = 0; i < 4; i++) {
            int e = t + i * 256;
            int row = e >> 4, c4 = (e & 15) * 4;
            int kk = k0 + row;
            float4 v = make_float4(0.f, 0.f, 0.f, 0.f);
            if (kk < K)
                v = *reinterpret_cast<const float4*>(&W[(size_t)kk * wld + c0 + c4]);
            uint4 u = make_uint4(f2tf(v.x), f2tf(v.y), f2tf(v.z), f2tf(v.w));
            *reinterpret_cast<uint4*>(&Bs[row * BP + c4]) = u;
        }
        __syncthreads();
        tile_mma64(As, Bs, wr, wc, g, l, acc);
        __syncthreads();
    }

    float* Yp; int ldy, syy; int colb;
    if (Y2 != nullptr && c0 >= N1) {
        Yp = Y2 + (size_t)z * zy2; ldy = ldy2; syy = sy2; colb = c0 - N1;
    } else {
        Yp = Y1 + (size_t)z * zy1; ldy = ldy1; syy = sy1; colb = c0;
    }

    #pragma unroll
    for (int mt = 0; mt < 2; mt++)
        #pragma unroll
        for (int idx = 0; idx < 4; idx++) {
            int row = r0 + wr * 32 + mt * 16 + g + ((idx >= 2) ? 8 : 0);
            #pragma unroll
            for (int nt = 0; nt < 4; nt++) {
                int col = colb + wc * 32 + nt * 8 + 2 * l + (idx & 1);
                Yp[(size_t)row * ldy + (size_t)col * syy] = acc[mt][nt][idx] * scale;
            }
        }
}

// ---------------- fused edge MLP (bucket-position order) ----------------
__global__ void __launch_bounds__(256) edge_mlp_kernel(
    const int* __restrict__ ei, const float* __restrict__ edge_attrs,
    const float* __restrict__ edge_feats, const float* __restrict__ Wd1)
{
    extern __shared__ uint32_t smem[];
    uint32_t* As = smem;
    uint32_t* Bs = smem + 128 * AP;
    float* sWd1 = (float*)(Bs + 64 * BP);
    int*   sSnd = (int*)(sWd1 + 64);
    int*   sRcv = sSnd + 128;
    int*   sEd  = sRcv + 128;
    float* sEf  = (float*)(sEd + 128);       // [128][8]
    float* sW8  = sEf + 128 * 8;             // [8][128]

    int t = threadIdx.x;
    int e0 = blockIdx.x * 128;               // position base
    int warp = t >> 5, lane = t & 31;
    int wr = warp >> 1, wc = warp & 1;
    int g = lane >> 2, l = lane & 3;

    if (t < 64) sWd1[t] = Wd1[t];
    if (t < 128) {
        int ed = g_BKT[e0 + t];
        sEd[t] = ed;
        int snd = ei[ed];
        sSnd[t] = snd;
        sRcv[t] = ei[EE + ed];
        g_PSND[e0 + t] = snd;
        g_PEA[e0 + t] = reinterpret_cast<const float4*>(edge_attrs)[ed];
    }
    #pragma unroll
    for (int i = 0; i < 4; i++) sW8[t + i * 256] = g_Wt8[t + i * 256];
    __syncthreads();

    // edge_feats rows by gathered index (32B per edge, L2-resident)
    {
        float4 v = *reinterpret_cast<const float4*>(
            &edge_feats[(size_t)sEd[t >> 1] * 8 + (t & 1) * 4]);
        reinterpret_cast<float4*>(sEf)[t] = v;
    }
    __syncthreads();

    // h0 = silu((ef8@W8[:, :64] + AS[snd] + AT[rcv]) * rs264) -> As
    #pragma unroll
    for (int i = 0; i < 32; i++) {
        int e = t + i * 256;
        int row = e >> 6, c = e & 63;
        float accv = 0.f;
        #pragma unroll
        for (int k = 0; k < 8; k++)
            accv = fmaf(sEf[row * 8 + k], sW8[k * 128 + c], accv);
        float h0 = (accv
                  + g_ABCD[(size_t)sSnd[row] * 256 + c]
                  + g_ABCD[(size_t)sRcv[row] * 256 + 64 + c]) * RS264;
        As[row * AP + c] = f2tf(siluf(h0));
    }
    // density head (cols 64..127 of packed W8)
    for (int el = warp; el < 128; el += 8) {
        int snd = sSnd[el], rcv = sRcv[el];
        float sum = 0.f;
        #pragma unroll
        for (int h = 0; h < 2; h++) {
            int c = lane + h * 32;
            float accv = 0.f;
            #pragma unroll
            for (int k = 0; k < 8; k++)
                accv = fmaf(sEf[el * 8 + k], sW8[k * 128 + 64 + c], accv);
            float d0 = (accv
                      + g_ABCD[(size_t)snd * 256 + 128 + c]
                      + g_ABCD[(size_t)rcv * 256 + 192 + c]) * RS264;
            sum += siluf(d0) * sWd1[c];
        }
        #pragma unroll
        for (int o = 16; o > 0; o >>= 1)
            sum += __shfl_down_sync(0xffffffff, sum, o);
        if (lane == 0) {
            float x = sum * RS64;
            g_ED[e0 + el] = tanhf(x * x);
        }
    }
    // W_r1 (pre-rounded tf32 bits: pure 16B copies)
    #pragma unroll
    for (int i = 0; i < 4; i++) {
        int e = t + i * 256;
        int row = e >> 4, c4 = (e & 15) * 4;
        uint4 u = *reinterpret_cast<const uint4*>(&g_Wr1t[row * 64 + c4]);
        *reinterpret_cast<uint4*>(&Bs[row * BP + c4]) = u;
    }
    __syncthreads();

    float acc[2][4][4] = {};
    tile_mma64(As, Bs, wr, wc, g, l, acc);
    __syncthreads();

    #pragma unroll
    for (int mt = 0; mt < 2; mt++)
        #pragma unroll
        for (int idx = 0; idx < 4; idx++) {
            int row = wr * 32 + mt * 16 + g + ((idx >= 2) ? 8 : 0);
            #pragma unroll
            for (int nt = 0; nt < 4; nt++) {
                int col = wc * 32 + nt * 8 + 2 * l + (idx & 1);
                As[row * AP + col] = f2tf(siluf(acc[mt][nt][idx] * RS64));
            }
        }
    #pragma unroll
    for (int i = 0; i < 4; i++) {
        int e = t + i * 256;
        int row = e >> 4, c4 = (e & 15) * 4;
        uint4 u = *reinterpret_cast<const uint4*>(&g_Wr2t[row * 64 + c4]);
        *reinterpret_cast<uint4*>(&Bs[row * BP + c4]) = u;
    }
    __syncthreads();

    float acc2[2][4][4] = {};
    tile_mma64(As, Bs, wr, wc, g, l, acc2);
    __syncthreads();

    #pragma unroll
    for (int mt = 0; mt < 2; mt++)
        #pragma unroll
        for (int idx = 0; idx < 4; idx++) {
            int row = wr * 32 + mt * 16 + g + ((idx >= 2) ? 8 : 0);
            #pragma unroll
            for (int nt = 0; nt < 4; nt++) {
                int col = wc * 32 + nt * 8 + 2 * l + (idx & 1);
                As[row * AP + col] = f2tf(siluf(acc2[mt][nt][idx] * RS64));
            }
        }
    __syncthreads();

    for (int ct = 0; ct < 8; ct++) {
        #pragma unroll
        for (int i = 0; i < 4; i++) {
            int e = t + i * 256;
            int row = e >> 4, c4 = (e & 15) * 4;
            uint4 u = *reinterpret_cast<const uint4*>(&g_Wr3t[row * 512 + ct * 64 + c4]);
            *reinterpret_cast<uint4*>(&Bs[row * BP + c4]) = u;
        }
        __syncthreads();
        float acc3[2][4][4] = {};
        tile_mma64(As, Bs, wr, wc, g, l, acc3);
        #pragma unroll
        for (int mt = 0; mt < 2; mt++)
            #pragma unroll
            for (int hi = 0; hi < 2; hi++) {
                int row = e0 + wr * 32 + mt * 16 + g + (hi ? 8 : 0);
                #pragma unroll
                for (int nt = 0; nt < 4; nt++) {
                    int col = ct * 64 + wc * 32 + nt * 8 + 2 * l;
                    __half2 h = __floats2half2_rn(acc3[mt][nt][hi * 2] * RS64,
                                                  acc3[mt][nt][hi * 2 + 1] * RS64);
                    *reinterpret_cast<__half2*>(&g_TPWh[(size_t)row * 512 + col]) = h;
                }
            }
        __syncthreads();
    }
}

// ---------------- weight prep (+ CNT zeroing folded in) ----------------
__global__ void __launch_bounds__(256) prep_kernel(
    const float* __restrict__ W_skip_s, const float* __restrict__ W_skip_v,
    const float* __restrict__ W_up_s,   const float* __restrict__ W_up_v,
    const float* __restrict__ W_src,    const float* __restrict__ W_tgt,
    const float* __restrict__ W_r0,     const float* __restrict__ W_d0,
    const float* __restrict__ W_r1,     const float* __restrict__ W_r2,
    const float* __restrict__ W_r3,
    const float* __restrict__ W1_s,     const float* __restrict__ W1_v,
    const float* __restrict__ Wres_s,   const float* __restrict__ Wres_v)
{
    int id = blockIdx.x * 256 + threadIdx.x;
    if (id < NN) g_CNT[id] = 0;
    if (id < 128 * 256) {
        int m = id >> 8, j = id & 255;
        g_Wns[id] = (j < 128) ? W_skip_s[m * 128 + j] : W_up_s[m * 128 + j - 128];
        g_Wnv[id] = (j < 128) ? W_skip_v[m * 128 + j] : W_up_v[m * 128 + j - 128];
    }
    if (id < 8 * 128) {
        int m = id >> 7, j = id & 127;
        g_Wt8[id] = (j < 64) ? W_r0[m * 64 + j] : W_d0[m * 64 + j - 64];
    }
    if (id < 384 * 256) {
        int k = id >> 8, j = id & 255;
        g_Wms[id] = (k < 256) ? W1_s[k * 256 + j] * RS256
                              : Wres_s[(k - 256) * 256 + j] * RS128;
    }
    if (id < 384 * 128) {
        int k = id / 128, j = id % 128;
        g_Wmv[id] = (k < 256) ? W1_v[k * 128 + j] * RS256
                              : Wres_v[(k - 256) * 128 + j] * RS128;
    }
    if (id < 64 * 64) {
        g_Wr1t[id] = f2tf(W_r1[id]);
        g_Wr2t[id] = f2tf(W_r2[id]);
    }
    if (id < 64 * 512) {
        g_Wr3t[id] = f2tf(W_r3[id]);
    }
    if (id < 10 * 256) {
        int a = id >> 8, j = id & 255;
        int q = j >> 6, jj = j & 63;
        const float* S = (q == 0 || q == 2) ? W_src : W_tgt;
        const float* M = (q < 2) ? W_r0 : W_d0;
        int off = (q == 0 || q == 2) ? 8 : 136;
        float s = 0.f;
        for (int m = 0; m < 128; m++)
            s += S[a * 128 + m] * M[(off + m) * 64 + jj];
        g_Wc[a * 256 + j] = s * RS10;
    }
}

// ---------------- bucketing ----------------
__global__ void count_kernel(const int* __restrict__ ei) {
    int e = blockIdx.x * blockDim.x + threadIdx.x;
    if (e < EE) atomicAdd(&g_CNT[ei[EE + e]], 1);
}
__global__ void __launch_bounds__(1024) scan_kernel() {
    __shared__ int wt[32];
    int t = threadIdx.x, lane = t & 31, w = t >> 5;
    int base = t * 8;
    int4 lo = reinterpret_cast<const int4*>(g_CNT)[t * 2];
    int4 hi = reinterpret_cast<const int4*>(g_CNT)[t * 2 + 1];
    int local[8] = {lo.x, lo.y, lo.z, lo.w, hi.x, hi.y, hi.z, hi.w};
    int s = 0;
    #pragma unroll
    for (int i = 0; i < 8; i++) s += local[i];
    int v = s;
    #pragma unroll
    for (int o = 1; o < 32; o <<= 1) {
        int u = __shfl_up_sync(0xffffffff, v, o);
        if (lane >= o) v += u;
    }
    if (lane == 31) wt[w] = v;
    __syncthreads();
    if (w == 0) {
        int x = wt[lane];
        #pragma unroll
        for (int o = 1; o < 32; o <<= 1) {
            int u = __shfl_up_sync(0xffffffff, x, o);
            if (lane >= o) x += u;
        }
        wt[lane] = x;
    }
    __syncthreads();
    int run = v - s + (w > 0 ? wt[w - 1] : 0);
    #pragma unroll
    for (int i = 0; i < 8; i++) { g_OFF[base + i] = run; g_CUR[base + i] = run; run += local[i]; }
    if (t == 1023) g_OFF[NN] = run;
}
__global__ void fill_kernel(const int* __restrict__ ei) {
    int e = blockIdx.x * blockDim.x + threadIdx.x;
    if (e < EE) {
        int pos = atomicAdd(&g_CUR[ei[EE + e]], 1);
        g_BKT[pos] = e;
    }
}
__global__ void sort_kernel() {
    int n = blockIdx.x * blockDim.x + threadIdx.x;
    if (n >= NN) return;
    int s = g_OFF[n], t = g_OFF[n + 1];
    for (int i = s + 1; i < t; i++) {
        int v = g_BKT[i];
        int j = i - 1;
        while (j >= s && g_BKT[j] > v) { g_BKT[j + 1] = g_BKT[j]; j--; }
        g_BKT[j + 1] = v;
    }
}

// ---------------- per-node gather (streaming, 2x unrolled) ----------------
__global__ void __launch_bounds__(256) gather_kernel(
    const float* __restrict__ alpha, const float* __restrict__ beta)
{
    __shared__ float red[256];
    int n = blockIdx.x;
    int j = threadIdx.x;
    int s = g_OFF[n], t = g_OFF[n + 1];
    float as = 0.f, av0 = 0.f, av1 = 0.f, av2 = 0.f;

    int jl = j & 127;
    bool spart = (j < 128);
    const float* xvbase = g_UV + jl * 3;

    int i = s;
    for (; i + 1 < t; i += 2) {
        int snd0 = g_PSND[i],     snd1 = g_PSND[i + 1];
        float4 y0 = g_PEA[i],     y1 = g_PEA[i + 1];
        const __half* tp0 = g_TPWh + (size_t)i * 512;
        const __half* tp1 = g_TPWh + (size_t)(i + 1) * 512;
        if (spart) {
            float w1a = __half2float(tp0[jl]),       w1b = __half2float(tp1[jl]);
            float w2a = __half2float(tp0[128 + jl]), w2b = __half2float(tp1[128 + jl]);
            float xsa = g_US[snd0 * 128 + jl],       xsb = g_US[snd1 * 128 + jl];
            as = fmaf(w1a * xsa, y0.x, as);
            float t2a = w2a * xsa * IS3;
            av0 = fmaf(t2a, y0.y, av0);
            av1 = fmaf(t2a, y0.z, av1);
            av2 = fmaf(t2a, y0.w, av2);
            as = fmaf(w1b * xsb, y1.x, as);
            float t2b = w2b * xsb * IS3;
            av0 = fmaf(t2b, y1.y, av0);
            av1 = fmaf(t2b, y1.z, av1);
            av2 = fmaf(t2b, y1.w, av2);
        } else {
            float w3a = __half2float(tp0[256 + jl]), w3b = __half2float(tp1[256 + jl]);
            float w4a = __half2float(tp0[384 + jl]), w4b = __half2float(tp1[384 + jl]);
            const float* xva = xvbase + snd0 * 384;
            const float* xvb = xvbase + snd1 * 384;
            float xa0 = xva[0], xa1 = xva[1], xa2 = xva[2];
            float xb0 = xvb[0], xb1 = xvb[1], xb2 = xvb[2];
            float sva = xa0 * y0.y + xa1 * y0.z + xa2 * y0.w;
            as = fmaf(w4a * IS3, sva, as);
            float t3a = w3a * y0.x * IS3;
            av0 = fmaf(t3a, xa0, av0);
            av1 = fmaf(t3a, xa1, av1);
            av2 = fmaf(t3a, xa2, av2);
            float svb = xb0 * y1.y + xb1 * y1.z + xb2 * y1.w;
            as = fmaf(w4b * IS3, svb, as);
            float t3b = w3b * y1.x * IS3;
            av0 = fmaf(t3b, xb0, av0);
            av1 = fmaf(t3b, xb1, av1);
            av2 = fmaf(t3b, xb2, av2);
        }
    }
    for (; i < t; i++) {
        int snd = g_PSND[i];
        float4 y = g_PEA[i];
        const __half* tp = g_TPWh + (size_t)i * 512;
        if (spart) {
            float w1 = __half2float(tp[jl]);
            float w2 = __half2float(tp[128 + jl]);
            float xs = g_US[snd * 128 + jl];
            as = fmaf(w1 * xs, y.x, as);
            float t2 = w2 * xs * IS3;
            av0 = fmaf(t2, y.y, av0);
            av1 = fmaf(t2, y.z, av1);
            av2 = fmaf(t2, y.w, av2);
        } else {
            float w3 = __half2float(tp[256 + jl]);
            float w4 = __half2float(tp[384 + jl]);
            const float* xv = xvbase + snd * 384;
            float x0 = xv[0], x1 = xv[1], x2 = xv[2];
            float sv = x0 * y.y + x1 * y.z + x2 * y.w;
            as = fmaf(w4 * IS3, sv, as);
            float t3 = w3 * y.x * IS3;
            av0 = fmaf(t3, x0, av0);
            av1 = fmaf(t3, x1, av1);
            av2 = fmaf(t3, x2, av2);
        }
    }
    float dsum = 0.f;
    for (int q = s + j; q < t; q += 256) dsum += g_ED[q];
    red[j] = dsum;
    __syncthreads();
    for (int o = 128; o > 0; o >>= 1) {
        if (j < o) red[j] += red[j + o];
        __syncthreads();
    }
    float invd = 1.f / (red[0] * beta[0] + alpha[0]);

    g_MSGS[n * 256 + j] = as * invd;
    g_MSGV[n * 768 + j * 3 + 0] = av0 * invd;
    g_MSGV[n * 768 + j * 3 + 1] = av1 * invd;
    g_MSGV[n * 768 + j * 3 + 2] = av2 * invd;
}

__global__ void act_kernel() {
    int idx = blockIdx.x * blockDim.x + threadIdx.x;
    int n = idx >> 7, u = idx & 127;
    float ms = g_MS[n * 256 + u];
    g_OS[n * 128 + u] = ms / (1.f + __expf(-ms));
    float sg = 1.f / (1.f + __expf(-g_MS[n * 256 + 128 + u]));
    int b = n * 384 + u * 3;
    g_OV[b + 0] = g_MV[b + 0] * sg;
    g_OV[b + 1] = g_MV[b + 1] * sg;
    g_OV[b + 2] = g_MV[b + 2] * sg;
}

// ---------------- host ----------------
static float* sym(const void* symbol) {
    void* p = nullptr;
    cudaGetSymbolAddress(&p, symbol);
    return (float*)p;
}

extern "C" void kernel_launch(void* const* d_in, const int* in_sizes, int n_in,
                              void* d_out, int out_size)
{
    const float* node_attrs = (const float*)d_in[0];
    const float* node_feats = (const float*)d_in[1];
    const float* edge_attrs = (const float*)d_in[2];
    const float* edge_feats = (const float*)d_in[3];
    const int*   ei         = (const int*)  d_in[4];
    const float* W_skip_s = (const float*)d_in[5];
    const float* W_skip_v = (const float*)d_in[6];
    const float* W_up_s   = (const float*)d_in[7];
    const float* W_up_v   = (const float*)d_in[8];
    const float* W_src    = (const float*)d_in[9];
    const float* W_tgt    = (const float*)d_in[10];
    const float* W_r0     = (const float*)d_in[11];
    const float* W_r1     = (const float*)d_in[12];
    const float* W_r2     = (const float*)d_in[13];
    const float* W_r3     = (const float*)d_in[14];
    const float* W_d0     = (const float*)d_in[15];
    const float* W_d1     = (const float*)d_in[16];
    const float* W1_s     = (const float*)d_in[17];
    const float* W1_v     = (const float*)d_in[18];
    const float* Wres_s   = (const float*)d_in[19];
    const float* Wres_v   = (const float*)d_in[20];
    const float* W2_s     = (const float*)d_in[21];
    const float* W2_v     = (const float*)d_in[22];
    const float* alpha    = (const float*)d_in[23];
    const float* beta     = (const float*)d_in[24];

    float* out    = (float*)d_out;
    float* out_sc = (float*)d_out + (size_t)NN * 512;

    float* US   = sym(g_US);   float* UV   = sym(g_UV);
    float* ABCD = sym(g_ABCD);
    float* MSGS = sym(g_MSGS); float* MSGV = sym(g_MSGV);
    float* MS   = sym(g_MS);   float* MV   = sym(g_MV);
    float* OS   = sym(g_OS);   float* OV   = sym(g_OV);
    float* Wns  = sym(g_Wns);  float* Wnv  = sym(g_Wnv);
    float* Wc   = sym(g_Wc);
    float* Wms  = sym(g_Wms);  float* Wmv  = sym(g_Wmv);

    cudaFuncSetAttribute(mma_gemm_kernel,
                         cudaFuncAttributeMaxDynamicSharedMemorySize, MMA_SMEM);
    cudaFuncSetAttribute(edge_mlp_kernel,
                         cudaFuncAttributeMaxDynamicSharedMemorySize, EDGE_SMEM);

    // side stream + fork/join events (created once; capture forks/joins via events)
    static cudaStream_t s_side = nullptr;
    static cudaEvent_t  s_ev[6] = {};
    if (s_side == nullptr) {
        cudaStreamCreateWithFlags(&s_side, cudaStreamNonBlocking);
        for (int i = 0; i < 6; i++)
            cudaEventCreateWithFlags(&s_ev[i], cudaEventDisableTiming);
    }

    dim3 B(256);
    const int BIG = 1 << 30;

    prep_kernel<<<384, B>>>(W_skip_s, W_skip_v, W_up_s, W_up_v, W_src, W_tgt,
                            W_r0, W_d0, W_r1, W_r2, W_r3,
                            W1_s, W1_v, Wres_s, Wres_v);

    // fork 1: bucketing chain + ABCD GEMM on side; node GEMMs on main
    cudaEventRecord(s_ev[0], 0);
    cudaStreamWaitEvent(s_side, s_ev[0], 0);

    count_kernel<<<EE / 256, B, 0, s_side>>>(ei);
    scan_kernel<<<1, 1024, 0, s_side>>>();
    fill_kernel<<<EE / 256, B, 0, s_side>>>(ei);
    sort_kernel<<<NN / 256, B, 0, s_side>>>();
    mma_gemm_kernel<<<dim3(4, 64), B, MMA_SMEM, s_side>>>(
        node_attrs, 10, 1, 0, nullptr, 0, 0, 0, BIG,
        Wc, 256, ABCD, 256, 1, 0, nullptr, 0, 0, 0, BIG, 10, 1.f);
    cudaEventRecord(s_ev[1], s_side);

    mma_gemm_kernel<<<dim3(4, 64), B, MMA_SMEM>>>(
        node_feats, 512, 1, 0, nullptr, 0, 0, 0, BIG,
        Wns, 256, out_sc, 512, 1, 0, US, 128, 1, 0, 128, 128, RS128);
    mma_gemm_kernel<<<dim3(4, 64, 3), B, MMA_SMEM>>>(
        node_feats + 128, 512, 3, 1, nullptr, 0, 0, 0, BIG,
        Wnv, 256, out_sc + 128, 512, 3, 1, UV, 384, 3, 1, 128, 128, RS128);

    // join 1: edge_mlp needs both branches
    cudaStreamWaitEvent(0, s_ev[1], 0);

    edge_mlp_kernel<<<EE / 128, B, EDGE_SMEM>>>(ei, edge_attrs, edge_feats, W_d1);

    gather_kernel<<<NN, B>>>(alpha, beta);

    // fork 2: MS on main, MV on side
    cudaEventRecord(s_ev[2], 0);
    cudaStreamWaitEvent(s_side, s_ev[2], 0);
    mma_gemm_kernel<<<dim3(2, 64, 3), B, MMA_SMEM, s_side>>>(
        MSGV, 768, 3, 1, UV, 384, 3, 1, 256,
        Wmv, 128, MV, 384, 3, 1, nullptr, 0, 0, 0, BIG, 384, 1.f);
    cudaEventRecord(s_ev[3], s_side);

    mma_gemm_kernel<<<dim3(4, 64), B, MMA_SMEM>>>(
        MSGS, 256, 1, 0, US, 128, 1, 0, 256,
        Wms, 256, MS, 256, 1, 0, nullptr, 0, 0, 0, BIG, 384, 1.f);

    // join 2: act needs MS and MV
    cudaStreamWaitEvent(0, s_ev[3], 0);

    act_kernel<<<NN * 128 / 256, B>>>();

    // fork 3: f_s on main, f_v on side
    cudaEventRecord(s_ev[4], 0);
    cudaStreamWaitEvent(s_side, s_ev[4], 0);
    mma_gemm_kernel<<<dim3(2, 64, 3), B, MMA_SMEM, s_side>>>(
        OV, 384, 3, 1, nullptr, 0, 0, 0, BIG,
        W2_v, 128, out + 1, 512, 4, 1, nullptr, 0, 0, 0, BIG, 128, RS128);
    cudaEventRecord(s_ev[5], s_side);

    mma_gemm_kernel<<<dim3(2, 64), B, MMA_SMEM>>>(
        OS, 128, 1, 0, nullptr, 0, 0, 0, BIG,
        W2_s, 128, out, 512, 4, 0, nullptr, 0, 0, 0, BIG, 128, RS128);

    // join 3: rejoin side branch before capture ends
    cudaStreamWaitEvent(0, s_ev[5], 0);
}